// round 2
// baseline (speedup 1.0000x reference)
#include <cuda_runtime.h>
#include <math.h>

#define B_   2
#define T_   2048
#define D_   2048
#define H_   16
#define HD_  128
#define M_   (B_ * T_)   // 4096

// ---------------- scratch (allocation-free: device globals) ----------------
__device__ float g_xn  [(size_t)B_ * T_ * D_];
__device__ float g_q   [(size_t)B_ * T_ * D_];   // [B,H,T,HD]
__device__ float g_k   [(size_t)B_ * T_ * D_];
__device__ float g_v   [(size_t)B_ * T_ * D_];
__device__ float g_attn[(size_t)B_ * T_ * D_];   // [B,T,D]

// ---------------------------- RMSNorm ---------------------------------------
__global__ __launch_bounds__(256) void rmsnorm_kernel(const float* __restrict__ x,
                                                      const float* __restrict__ w,
                                                      float* __restrict__ out)
{
    int row = blockIdx.x;                      // 0..4095
    const float* xr = x + (size_t)row * D_;
    float* orow = out + (size_t)row * D_;
    int tid = threadIdx.x;

    float s = 0.f;
#pragma unroll
    for (int c = tid * 4; c < D_; c += 256 * 4) {
        float4 v = *(const float4*)(xr + c);
        s += v.x * v.x + v.y * v.y + v.z * v.z + v.w * v.w;
    }
#pragma unroll
    for (int m = 16; m; m >>= 1) s += __shfl_xor_sync(0xffffffffu, s, m);

    __shared__ float red[8];
    __shared__ float totsh;
    if ((tid & 31) == 0) red[tid >> 5] = s;
    __syncthreads();
    if (tid == 0) {
        float t = 0.f;
#pragma unroll
        for (int i = 0; i < 8; i++) t += red[i];
        totsh = t;
    }
    __syncthreads();

    float norm = sqrtf(totsh) * 0.022097086912079608f;  // * D^-0.5
    float inv  = 1.0f / (norm + 1e-8f);

#pragma unroll
    for (int c = tid * 4; c < D_; c += 256 * 4) {
        float4 v  = *(const float4*)(xr + c);
        float4 wv = *(const float4*)(w + c);
        float4 o;
        o.x = wv.x * v.x * inv;  o.y = wv.y * v.y * inv;
        o.z = wv.z * v.z * inv;  o.w = wv.w * v.w * inv;
        *(float4*)(orow + c) = o;
    }
}

// ------------------- SGEMM  C[M,N] = A[M,K] * B[N,K]^T ----------------------
// BM=BN=128, BK=8, 256 threads, 8x8 per thread.
// epi==1: scatter n->(h,hd), m->(b,t): C laid out as [B,H,T,HD]
// epi==0: plain row-major [M,N]
__global__ __launch_bounds__(256, 2) void sgemm_nt(const float* __restrict__ A,
                                                   const float* __restrict__ Bw,
                                                   float* __restrict__ C,
                                                   int epi)
{
    const int K = 2048;
    __shared__ float As[8][132];   // 132: float4-aligned rows + disjoint store banks
    __shared__ float Bs[8][132];

    int tid = threadIdx.x;
    int m0 = blockIdx.y * 128, n0 = blockIdx.x * 128;

    int lr = tid >> 1;             // 0..127 row within tile
    int lk = (tid & 1) << 2;       // 0 or 4
    const float* Ap = A  + (size_t)(m0 + lr) * K + lk;
    const float* Bp = Bw + (size_t)(n0 + lr) * K + lk;

    float acc[8][8];
#pragma unroll
    for (int i = 0; i < 8; i++)
#pragma unroll
        for (int j = 0; j < 8; j++) acc[i][j] = 0.f;

    int tx = tid & 15, ty = tid >> 4;

    for (int kt = 0; kt < K; kt += 8) {
        float4 av = *(const float4*)(Ap + kt);
        float4 bv = *(const float4*)(Bp + kt);
        As[lk + 0][lr] = av.x; As[lk + 1][lr] = av.y;
        As[lk + 2][lr] = av.z; As[lk + 3][lr] = av.w;
        Bs[lk + 0][lr] = bv.x; Bs[lk + 1][lr] = bv.y;
        Bs[lk + 2][lr] = bv.z; Bs[lk + 3][lr] = bv.w;
        __syncthreads();

#pragma unroll
        for (int kk = 0; kk < 8; kk++) {
            float4 a0 = *(const float4*)&As[kk][ty * 8];
            float4 a1 = *(const float4*)&As[kk][ty * 8 + 4];
            float4 b0 = *(const float4*)&Bs[kk][tx * 8];
            float4 b1 = *(const float4*)&Bs[kk][tx * 8 + 4];
            float a[8] = {a0.x, a0.y, a0.z, a0.w, a1.x, a1.y, a1.z, a1.w};
            float b[8] = {b0.x, b0.y, b0.z, b0.w, b1.x, b1.y, b1.z, b1.w};
#pragma unroll
            for (int i = 0; i < 8; i++)
#pragma unroll
                for (int j = 0; j < 8; j++) acc[i][j] += a[i] * b[j];
        }
        __syncthreads();
    }

#pragma unroll
    for (int i = 0; i < 8; i++) {
        int m = m0 + ty * 8 + i;
        float* dst;
        if (epi) {
            int b = m >> 11, t = m & (T_ - 1);
            int h = n0 >> 7;                       // hd base = tx*8 (n0 is 128-aligned)
            dst = C + (((size_t)((b * H_ + h) * T_ + t)) << 7) + tx * 8;
        } else {
            dst = C + (size_t)m * D_ + n0 + tx * 8;
        }
        float4 o0 = {acc[i][0], acc[i][1], acc[i][2], acc[i][3]};
        float4 o1 = {acc[i][4], acc[i][5], acc[i][6], acc[i][7]};
        *(float4*)dst = o0;
        *(float4*)(dst + 4) = o1;
    }
}

// ------------------------- Flash attention (causal) -------------------------
// Br=Bc=64, HD=128, 256 threads. Per-thread: 4x4 S tile, 4 rows x 8 cols of O.
// Dynamic smem layout: Qs[64][129] | Ks[64][129] | Vs[64][128] | Ps[64][65]
#define FLASH_SMEM_FLOATS (2 * 64 * 129 + 64 * 128 + 64 * 65)
#define FLASH_SMEM_BYTES  (FLASH_SMEM_FLOATS * 4)

__global__ __launch_bounds__(256) void flash_kernel(const float* __restrict__ Q,
                                                    const float* __restrict__ K,
                                                    const float* __restrict__ V,
                                                    float* __restrict__ O)
{
    extern __shared__ float sm[];
    float (*Qs)[129] = (float (*)[129])sm;
    float (*Ks)[129] = (float (*)[129])(sm + 64 * 129);
    float (*Vs)[128] = (float (*)[128])(sm + 2 * 64 * 129);
    float (*Ps)[65]  = (float (*)[65]) (sm + 2 * 64 * 129 + 64 * 128);

    int qt = blockIdx.x;          // q tile 0..31
    int bh = blockIdx.y;          // b*H + h
    int q0 = qt * 64;
    const float* Qp = Q + (size_t)bh * T_ * HD_;
    const float* Kp = K + (size_t)bh * T_ * HD_;
    const float* Vp = V + (size_t)bh * T_ * HD_;

    int tid = threadIdx.x;
    int tc = tid & 15, tr = tid >> 4;
    const float scale = 0.08838834764831845f;   // HD^-0.5

    // load + pre-scale Q tile
    for (int i = tid; i < 64 * 32; i += 256) {
        int r = i >> 5, c = (i & 31) << 2;
        float4 v = *(const float4*)(Qp + (size_t)(q0 + r) * HD_ + c);
        Qs[r][c]     = v.x * scale;  Qs[r][c + 1] = v.y * scale;
        Qs[r][c + 2] = v.z * scale;  Qs[r][c + 3] = v.w * scale;
    }

    float m_i[4], l_i[4], acc[4][8];
#pragma unroll
    for (int i = 0; i < 4; i++) {
        m_i[i] = -1e30f;  l_i[i] = 0.f;
#pragma unroll
        for (int c = 0; c < 8; c++) acc[i][c] = 0.f;
    }

    int nkt = qt + 1;  // causal: only tiles with k0 <= q0
    for (int kt = 0; kt < nkt; kt++) {
        int k0 = kt * 64;
        __syncthreads();   // previous iteration done with Ks/Vs/Ps
        for (int i = tid; i < 64 * 32; i += 256) {
            int r = i >> 5, c = (i & 31) << 2;
            float4 kv = *(const float4*)(Kp + (size_t)(k0 + r) * HD_ + c);
            Ks[r][c]     = kv.x;  Ks[r][c + 1] = kv.y;
            Ks[r][c + 2] = kv.z;  Ks[r][c + 3] = kv.w;
            float4 vv = *(const float4*)(Vp + (size_t)(k0 + r) * HD_ + c);
            *(float4*)&Vs[r][c] = vv;
        }
        __syncthreads();

        // S = (Q*scale) @ K^T   (4x4 per thread)
        float s[4][4];
#pragma unroll
        for (int i = 0; i < 4; i++)
#pragma unroll
            for (int j = 0; j < 4; j++) s[i][j] = 0.f;

#pragma unroll 8
        for (int k = 0; k < 128; k++) {
            float a0 = Qs[tr * 4 + 0][k], a1 = Qs[tr * 4 + 1][k];
            float a2 = Qs[tr * 4 + 2][k], a3 = Qs[tr * 4 + 3][k];
            float b0 = Ks[tc * 4 + 0][k], b1 = Ks[tc * 4 + 1][k];
            float b2 = Ks[tc * 4 + 2][k], b3 = Ks[tc * 4 + 3][k];
            s[0][0] += a0 * b0; s[0][1] += a0 * b1; s[0][2] += a0 * b2; s[0][3] += a0 * b3;
            s[1][0] += a1 * b0; s[1][1] += a1 * b1; s[1][2] += a1 * b2; s[1][3] += a1 * b3;
            s[2][0] += a2 * b0; s[2][1] += a2 * b1; s[2][2] += a2 * b2; s[2][3] += a2 * b3;
            s[3][0] += a3 * b0; s[3][1] += a3 * b1; s[3][2] += a3 * b2; s[3][3] += a3 * b3;
        }

        if (kt == qt) {  // diagonal tile: causal mask
#pragma unroll
            for (int i = 0; i < 4; i++)
#pragma unroll
                for (int j = 0; j < 4; j++)
                    if (k0 + tc * 4 + j > q0 + tr * 4 + i) s[i][j] = -1e30f;
        }

        // online softmax (row groups = 16 lanes within warp half)
#pragma unroll
        for (int i = 0; i < 4; i++) {
            float mt = fmaxf(fmaxf(s[i][0], s[i][1]), fmaxf(s[i][2], s[i][3]));
            mt = fmaxf(mt, __shfl_xor_sync(0xffffffffu, mt, 1));
            mt = fmaxf(mt, __shfl_xor_sync(0xffffffffu, mt, 2));
            mt = fmaxf(mt, __shfl_xor_sync(0xffffffffu, mt, 4));
            mt = fmaxf(mt, __shfl_xor_sync(0xffffffffu, mt, 8));
            float mnew  = fmaxf(m_i[i], mt);
            float alpha = __expf(m_i[i] - mnew);
            float ps = 0.f;
#pragma unroll
            for (int j = 0; j < 4; j++) {
                s[i][j] = __expf(s[i][j] - mnew);
                ps += s[i][j];
            }
            ps += __shfl_xor_sync(0xffffffffu, ps, 1);
            ps += __shfl_xor_sync(0xffffffffu, ps, 2);
            ps += __shfl_xor_sync(0xffffffffu, ps, 4);
            ps += __shfl_xor_sync(0xffffffffu, ps, 8);
            l_i[i] = l_i[i] * alpha + ps;
            m_i[i] = mnew;
#pragma unroll
            for (int c = 0; c < 8; c++) acc[i][c] *= alpha;
            Ps[tr * 4 + i][tc * 4 + 0] = s[i][0];
            Ps[tr * 4 + i][tc * 4 + 1] = s[i][1];
            Ps[tr * 4 + i][tc * 4 + 2] = s[i][2];
            Ps[tr * 4 + i][tc * 4 + 3] = s[i][3];
        }
        __syncthreads();

        // O += P @ V
#pragma unroll 4
        for (int j = 0; j < 64; j++) {
            float4 v0 = *(const float4*)&Vs[j][tc * 8];
            float4 v1 = *(const float4*)&Vs[j][tc * 8 + 4];
            float p0 = Ps[tr * 4 + 0][j], p1 = Ps[tr * 4 + 1][j];
            float p2 = Ps[tr * 4 + 2][j], p3 = Ps[tr * 4 + 3][j];
            acc[0][0] += p0 * v0.x; acc[0][1] += p0 * v0.y; acc[0][2] += p0 * v0.z; acc[0][3] += p0 * v0.w;
            acc[0][4] += p0 * v1.x; acc[0][5] += p0 * v1.y; acc[0][6] += p0 * v1.z; acc[0][7] += p0 * v1.w;
            acc[1][0] += p1 * v0.x; acc[1][1] += p1 * v0.y; acc[1][2] += p1 * v0.z; acc[1][3] += p1 * v0.w;
            acc[1][4] += p1 * v1.x; acc[1][5] += p1 * v1.y; acc[1][6] += p1 * v1.z; acc[1][7] += p1 * v1.w;
            acc[2][0] += p2 * v0.x; acc[2][1] += p2 * v0.y; acc[2][2] += p2 * v0.z; acc[2][3] += p2 * v0.w;
            acc[2][4] += p2 * v1.x; acc[2][5] += p2 * v1.y; acc[2][6] += p2 * v1.z; acc[2][7] += p2 * v1.w;
            acc[3][0] += p3 * v0.x; acc[3][1] += p3 * v0.y; acc[3][2] += p3 * v0.z; acc[3][3] += p3 * v0.w;
            acc[3][4] += p3 * v1.x; acc[3][5] += p3 * v1.y; acc[3][6] += p3 * v1.z; acc[3][7] += p3 * v1.w;
        }
    }

    // epilogue: normalize and scatter into [B,T,D]
    int b = bh >> 4, h = bh & 15;
#pragma unroll
    for (int i = 0; i < 4; i++) {
        float inv = 1.0f / l_i[i];
        int qrow = q0 + tr * 4 + i;
        float* dst = O + (size_t)(b * T_ + qrow) * D_ + h * HD_ + tc * 8;
        float4 o0 = {acc[i][0] * inv, acc[i][1] * inv, acc[i][2] * inv, acc[i][3] * inv};
        float4 o1 = {acc[i][4] * inv, acc[i][5] * inv, acc[i][6] * inv, acc[i][7] * inv};
        *(float4*)dst = o0;
        *(float4*)(dst + 4) = o1;
    }
}

// ------------------------------- launcher -----------------------------------
extern "C" void kernel_launch(void* const* d_in, const int* in_sizes, int n_in,
                              void* d_out, int out_size)
{
    const float* x      = (const float*)d_in[0];
    // d_in[1] = attn_mask (deterministic causal; applied analytically)
    const float* w_norm = (const float*)d_in[2];
    const float* wq     = (const float*)d_in[3];
    const float* wk     = (const float*)d_in[4];
    const float* wv     = (const float*)d_in[5];
    const float* wo     = (const float*)d_in[6];
    float* out = (float*)d_out;

    void *pxn, *pq, *pk, *pv, *pa;
    cudaGetSymbolAddress(&pxn, g_xn);
    cudaGetSymbolAddress(&pq,  g_q);
    cudaGetSymbolAddress(&pk,  g_k);
    cudaGetSymbolAddress(&pv,  g_v);
    cudaGetSymbolAddress(&pa,  g_attn);
    float* xn   = (float*)pxn;
    float* q    = (float*)pq;
    float* k    = (float*)pk;
    float* v    = (float*)pv;
    float* attn = (float*)pa;

    cudaFuncSetAttribute(flash_kernel,
                         cudaFuncAttributeMaxDynamicSharedMemorySize,
                         FLASH_SMEM_BYTES);

    // 1) RMSNorm
    rmsnorm_kernel<<<M_, 256>>>(x, w_norm, xn);

    // 2) Q/K/V projections (scatter to [B,H,T,HD])
    dim3 gemm_grid(D_ / 128, M_ / 128);
    sgemm_nt<<<gemm_grid, 256>>>(xn, wq, q, 1);
    sgemm_nt<<<gemm_grid, 256>>>(xn, wk, k, 1);
    sgemm_nt<<<gemm_grid, 256>>>(xn, wv, v, 1);

    // 3) causal flash attention -> [B,T,D]
    dim3 fgrid(T_ / 64, B_ * H_);
    flash_kernel<<<fgrid, 256, FLASH_SMEM_BYTES>>>(q, k, v, attn);

    // 4) output projection -> d_out
    sgemm_nt<<<gemm_grid, 256>>>(attn, wo, out, 0);
}

// round 4
// speedup vs baseline: 3.0152x; 3.0152x over previous
#include <cuda_runtime.h>
#include <cuda_bf16.h>
#include <cstdint>
#include <math.h>

#define B_   2
#define T_   2048
#define D_   2048
#define H_   16
#define HD_  128
#define M_   (B_ * T_)   // 4096
#define K_   2048

// ---------------- scratch (allocation-free: device globals) ----------------
__device__ __nv_bfloat16 g_xnh[(size_t)M_ * D_];
__device__ __nv_bfloat16 g_xnl[(size_t)M_ * D_];
__device__ __nv_bfloat16 g_wh [4][(size_t)D_ * D_];   // q,k,v,o
__device__ __nv_bfloat16 g_wl [4][(size_t)D_ * D_];
__device__ float g_q   [(size_t)M_ * D_];   // [B,H,T,HD]
__device__ float g_k   [(size_t)M_ * D_];
__device__ float g_v   [(size_t)M_ * D_];
__device__ float g_attn[(size_t)M_ * D_];   // [B,T,D]
__device__ __nv_bfloat16 g_ah[(size_t)M_ * D_];
__device__ __nv_bfloat16 g_al[(size_t)M_ * D_];

// ------------------------- PTX helpers (baseline sm_103 ISA) ----------------
__device__ __forceinline__ uint32_t smem_u32(const void* p) {
    uint32_t a;
    asm("{ .reg .u64 t; cvta.to.shared.u64 t, %1; cvt.u32.u64 %0, t; }" : "=r"(a) : "l"(p));
    return a;
}

#define CP_ASYNC16(dst, src) \
    asm volatile("cp.async.cg.shared.global [%0], [%1], 16;" :: "r"(dst), "l"(src))
#define CP_COMMIT() asm volatile("cp.async.commit_group;" ::: "memory")
#define CP_WAIT(n)  asm volatile("cp.async.wait_group %0;" :: "n"(n) : "memory")

#define LDSM_X4(r0, r1, r2, r3, a) \
    asm volatile("ldmatrix.sync.aligned.m8n8.x4.shared.b16 {%0,%1,%2,%3}, [%4];" \
                 : "=r"(r0), "=r"(r1), "=r"(r2), "=r"(r3) : "r"(a))

#define MMA16816(d, a0, a1, a2, a3, b0, b1) \
    asm volatile("mma.sync.aligned.m16n8k16.row.col.f32.bf16.bf16.f32 " \
                 "{%0,%1,%2,%3}, {%4,%5,%6,%7}, {%8,%9}, {%0,%1,%2,%3};" \
                 : "+f"((d)[0]), "+f"((d)[1]), "+f"((d)[2]), "+f"((d)[3]) \
                 : "r"(a0), "r"(a1), "r"(a2), "r"(a3), "r"(b0), "r"(b1))

// ---------------------- RMSNorm + split to bf16 hi/lo -----------------------
__global__ __launch_bounds__(256) void rmsnorm_split_kernel(const float* __restrict__ x,
                                                            const float* __restrict__ w,
                                                            __nv_bfloat16* __restrict__ hi,
                                                            __nv_bfloat16* __restrict__ lo)
{
    int row = blockIdx.x;
    const float* xr = x + (size_t)row * D_;
    int tid = threadIdx.x;

    float s = 0.f;
#pragma unroll
    for (int c = tid * 4; c < D_; c += 256 * 4) {
        float4 v = *(const float4*)(xr + c);
        s += v.x * v.x + v.y * v.y + v.z * v.z + v.w * v.w;
    }
#pragma unroll
    for (int m = 16; m; m >>= 1) s += __shfl_xor_sync(0xffffffffu, s, m);

    __shared__ float red[8];
    __shared__ float totsh;
    if ((tid & 31) == 0) red[tid >> 5] = s;
    __syncthreads();
    if (tid == 0) {
        float t = 0.f;
#pragma unroll
        for (int i = 0; i < 8; i++) t += red[i];
        totsh = t;
    }
    __syncthreads();

    float norm = sqrtf(totsh) * 0.022097086912079608f;  // * D^-0.5
    float inv  = 1.0f / (norm + 1e-8f);

#pragma unroll
    for (int c = tid * 4; c < D_; c += 256 * 4) {
        float4 v  = *(const float4*)(xr + c);
        float4 wv = *(const float4*)(w + c);
        float o[4] = {wv.x * v.x * inv, wv.y * v.y * inv, wv.z * v.z * inv, wv.w * v.w * inv};
#pragma unroll
        for (int j = 0; j < 4; j++) {
            __nv_bfloat16 h = __float2bfloat16_rn(o[j]);
            float r = o[j] - __bfloat162float(h);
            hi[(size_t)row * D_ + c + j] = h;
            lo[(size_t)row * D_ + c + j] = __float2bfloat16_rn(r);
        }
    }
}

// -------------------------- fp32 -> bf16 hi/lo split ------------------------
__global__ __launch_bounds__(256) void split_kernel(const float* __restrict__ x,
                                                    __nv_bfloat16* __restrict__ hi,
                                                    __nv_bfloat16* __restrict__ lo,
                                                    int n4)
{
    int i = blockIdx.x * 256 + threadIdx.x;
    if (i >= n4) return;
    float4 v = ((const float4*)x)[i];
    float a[4] = {v.x, v.y, v.z, v.w};
    __nv_bfloat16 h[4], l[4];
#pragma unroll
    for (int j = 0; j < 4; j++) {
        h[j] = __float2bfloat16_rn(a[j]);
        l[j] = __float2bfloat16_rn(a[j] - __bfloat162float(h[j]));
    }
    ((__nv_bfloat162*)hi)[i * 2 + 0] = __nv_bfloat162(h[0], h[1]);
    ((__nv_bfloat162*)hi)[i * 2 + 1] = __nv_bfloat162(h[2], h[3]);
    ((__nv_bfloat162*)lo)[i * 2 + 0] = __nv_bfloat162(l[0], l[1]);
    ((__nv_bfloat162*)lo)[i * 2 + 1] = __nv_bfloat162(l[2], l[3]);
}

// ------ warp-MMA GEMM: C[M,N] = (Ah+Al)[M,K] @ (Bh+Bl)[N,K]^T  (bf16x3) -----
// CTA 128x128, K-chunk 32, 8 warps (2 M x 4 N), warp tile 64x32.
// Smem rows padded to 80B (conflict-free ldmatrix). cp.async double buffering.
#define SROW     80                      // bytes per 32-bf16 row
#define TILE_B   (128 * SROW)            // 10240 B per operand tile
#define STAGE_B  (4 * TILE_B)            // Ah, Al, Bh, Bl
#define GEMM_SMEM (2 * STAGE_B)          // 81920 B

__device__ __forceinline__ void gemm_issue_loads(uint32_t sb, int stage,
                                                 const __nv_bfloat16* Ah,
                                                 const __nv_bfloat16* Al,
                                                 const __nv_bfloat16* Bh,
                                                 const __nv_bfloat16* Bl,
                                                 int m0, int n0, int k0, int tid)
{
    const __nv_bfloat16* srcs[4] = {Ah, Al, Bh, Bl};
    uint32_t base = sb + stage * STAGE_B;
#pragma unroll
    for (int it = 0; it < 8; ++it) {
        int i = tid + it * 256;          // 0..2047
        int tile = i >> 9;               // 0..3
        int j = i & 511;                 // 0..511
        int r = j >> 2, cv = j & 3;
        int row0 = (tile < 2) ? m0 : n0;
        const __nv_bfloat16* src = srcs[tile] + (size_t)(row0 + r) * K_ + k0 + cv * 8;
        CP_ASYNC16(base + tile * TILE_B + r * SROW + cv * 16, src);
    }
}

__global__ __launch_bounds__(256, 2) void gemm_mma(const __nv_bfloat16* __restrict__ Ah,
                                                   const __nv_bfloat16* __restrict__ Al,
                                                   const __nv_bfloat16* __restrict__ Bh,
                                                   const __nv_bfloat16* __restrict__ Bl,
                                                   float* __restrict__ C,
                                                   int epi)
{
    extern __shared__ char smem[];
    uint32_t sb = smem_u32(smem);
    int tid = threadIdx.x, wid = tid >> 5, lane = tid & 31;
    int m0 = blockIdx.y * 128, n0 = blockIdx.x * 128;
    int warpM = wid & 1, warpN = wid >> 1;    // 2 x 4

    float acc[4][4][4];
#pragma unroll
    for (int i = 0; i < 4; i++)
#pragma unroll
        for (int j = 0; j < 4; j++)
#pragma unroll
            for (int c = 0; c < 4; c++) acc[i][j][c] = 0.f;

    // per-lane ldmatrix base offsets (within a tile)
    int aRow = warpM * 64 + (lane & 15);      // + fm*16
    int aColHalf = (lane >> 4) * 8;           // k sub-offset
    int bMat = lane >> 3, bRowIn = lane & 7;
    int bRow = warpN * 32 + (bMat >> 1) * 8 + bRowIn;   // + g*16
    int bColHalf = (bMat & 1) * 8;

    const int NCHUNK = K_ / 32;               // 64

    gemm_issue_loads(sb, 0, Ah, Al, Bh, Bl, m0, n0, 0, tid);
    CP_COMMIT();

    for (int c = 0; c < NCHUNK; ++c) {
        if (c + 1 < NCHUNK) {
            gemm_issue_loads(sb, (c + 1) & 1, Ah, Al, Bh, Bl, m0, n0, (c + 1) * 32, tid);
            CP_COMMIT();
            CP_WAIT(1);
        } else {
            CP_WAIT(0);
        }
        __syncthreads();

        uint32_t st = sb + (c & 1) * STAGE_B;
        uint32_t tAh = st, tAl = st + TILE_B, tBh = st + 2 * TILE_B, tBl = st + 3 * TILE_B;

#pragma unroll
        for (int kk = 0; kk < 32; kk += 16) {
            uint32_t a[4][4], bh[4][2], bl[4][2];
            // A-hi fragments
#pragma unroll
            for (int fm = 0; fm < 4; fm++) {
                uint32_t ad = tAh + (aRow + fm * 16) * SROW + (kk + aColHalf) * 2;
                LDSM_X4(a[fm][0], a[fm][1], a[fm][2], a[fm][3], ad);
            }
            // B-hi / B-lo fragments (x4 covers two fn each)
#pragma unroll
            for (int g = 0; g < 2; g++) {
                uint32_t bd = tBh + (bRow + g * 16) * SROW + (kk + bColHalf) * 2;
                LDSM_X4(bh[2 * g][0], bh[2 * g][1], bh[2 * g + 1][0], bh[2 * g + 1][1], bd);
                uint32_t bd2 = tBl + (bRow + g * 16) * SROW + (kk + bColHalf) * 2;
                LDSM_X4(bl[2 * g][0], bl[2 * g][1], bl[2 * g + 1][0], bl[2 * g + 1][1], bd2);
            }
            // hh pass
#pragma unroll
            for (int fm = 0; fm < 4; fm++)
#pragma unroll
                for (int fn = 0; fn < 4; fn++)
                    MMA16816(acc[fm][fn], a[fm][0], a[fm][1], a[fm][2], a[fm][3],
                             bh[fn][0], bh[fn][1]);
            // hl pass
#pragma unroll
            for (int fm = 0; fm < 4; fm++)
#pragma unroll
                for (int fn = 0; fn < 4; fn++)
                    MMA16816(acc[fm][fn], a[fm][0], a[fm][1], a[fm][2], a[fm][3],
                             bl[fn][0], bl[fn][1]);
            // A-lo fragments (reuse a[] registers)
#pragma unroll
            for (int fm = 0; fm < 4; fm++) {
                uint32_t ad = tAl + (aRow + fm * 16) * SROW + (kk + aColHalf) * 2;
                LDSM_X4(a[fm][0], a[fm][1], a[fm][2], a[fm][3], ad);
            }
            // lh pass
#pragma unroll
            for (int fm = 0; fm < 4; fm++)
#pragma unroll
                for (int fn = 0; fn < 4; fn++)
                    MMA16816(acc[fm][fn], a[fm][0], a[fm][1], a[fm][2], a[fm][3],
                             bh[fn][0], bh[fn][1]);
        }
        __syncthreads();
    }

    // ---------------- epilogue: write fp32 C --------------------------------
#pragma unroll
    for (int fm = 0; fm < 4; fm++) {
#pragma unroll
        for (int fn = 0; fn < 4; fn++) {
            int m = m0 + warpM * 64 + fm * 16 + (lane >> 2);
            int n = n0 + warpN * 32 + fn * 8 + (lane & 3) * 2;
#pragma unroll
            for (int half = 0; half < 2; half++) {
                int mr = m + half * 8;
                float* dst;
                if (epi) {
                    int b = mr >> 11, t = mr & (T_ - 1);
                    int h = n >> 7, hd = n & (HD_ - 1);
                    dst = C + (((size_t)((b * H_ + h) * T_ + t)) << 7) + hd;
                } else {
                    dst = C + (size_t)mr * D_ + n;
                }
                float2 o = {acc[fm][fn][half * 2], acc[fm][fn][half * 2 + 1]};
                *(float2*)dst = o;
            }
        }
    }
}

// ------------------------- Flash attention (causal) -------------------------
#define FLASH_SMEM_FLOATS (2 * 64 * 129 + 64 * 128 + 64 * 65)
#define FLASH_SMEM_BYTES  (FLASH_SMEM_FLOATS * 4)

__global__ __launch_bounds__(256) void flash_kernel(const float* __restrict__ Q,
                                                    const float* __restrict__ K,
                                                    const float* __restrict__ V,
                                                    float* __restrict__ O)
{
    extern __shared__ float sm[];
    float (*Qs)[129] = (float (*)[129])sm;
    float (*Ks)[129] = (float (*)[129])(sm + 64 * 129);
    float (*Vs)[128] = (float (*)[128])(sm + 2 * 64 * 129);
    float (*Ps)[65]  = (float (*)[65]) (sm + 2 * 64 * 129 + 64 * 128);

    int qt = blockIdx.x;
    int bh = blockIdx.y;
    int q0 = qt * 64;
    const float* Qp = Q + (size_t)bh * T_ * HD_;
    const float* Kp = K + (size_t)bh * T_ * HD_;
    const float* Vp = V + (size_t)bh * T_ * HD_;

    int tid = threadIdx.x;
    int tc = tid & 15, tr = tid >> 4;
    const float scale = 0.08838834764831845f;

    for (int i = tid; i < 64 * 32; i += 256) {
        int r = i >> 5, c = (i & 31) << 2;
        float4 v = *(const float4*)(Qp + (size_t)(q0 + r) * HD_ + c);
        Qs[r][c]     = v.x * scale;  Qs[r][c + 1] = v.y * scale;
        Qs[r][c + 2] = v.z * scale;  Qs[r][c + 3] = v.w * scale;
    }

    float m_i[4], l_i[4], acc[4][8];
#pragma unroll
    for (int i = 0; i < 4; i++) {
        m_i[i] = -1e30f;  l_i[i] = 0.f;
#pragma unroll
        for (int c = 0; c < 8; c++) acc[i][c] = 0.f;
    }

    int nkt = qt + 1;
    for (int kt = 0; kt < nkt; kt++) {
        int k0 = kt * 64;
        __syncthreads();
        for (int i = tid; i < 64 * 32; i += 256) {
            int r = i >> 5, c = (i & 31) << 2;
            float4 kv = *(const float4*)(Kp + (size_t)(k0 + r) * HD_ + c);
            Ks[r][c]     = kv.x;  Ks[r][c + 1] = kv.y;
            Ks[r][c + 2] = kv.z;  Ks[r][c + 3] = kv.w;
            float4 vv = *(const float4*)(Vp + (size_t)(k0 + r) * HD_ + c);
            *(float4*)&Vs[r][c] = vv;
        }
        __syncthreads();

        float s[4][4];
#pragma unroll
        for (int i = 0; i < 4; i++)
#pragma unroll
            for (int j = 0; j < 4; j++) s[i][j] = 0.f;

#pragma unroll 8
        for (int k = 0; k < 128; k++) {
            float a0 = Qs[tr * 4 + 0][k], a1 = Qs[tr * 4 + 1][k];
            float a2 = Qs[tr * 4 + 2][k], a3 = Qs[tr * 4 + 3][k];
            float b0 = Ks[tc * 4 + 0][k], b1 = Ks[tc * 4 + 1][k];
            float b2 = Ks[tc * 4 + 2][k], b3 = Ks[tc * 4 + 3][k];
            s[0][0] += a0 * b0; s[0][1] += a0 * b1; s[0][2] += a0 * b2; s[0][3] += a0 * b3;
            s[1][0] += a1 * b0; s[1][1] += a1 * b1; s[1][2] += a1 * b2; s[1][3] += a1 * b3;
            s[2][0] += a2 * b0; s[2][1] += a2 * b1; s[2][2] += a2 * b2; s[2][3] += a2 * b3;
            s[3][0] += a3 * b0; s[3][1] += a3 * b1; s[3][2] += a3 * b2; s[3][3] += a3 * b3;
        }

        if (kt == qt) {
#pragma unroll
            for (int i = 0; i < 4; i++)
#pragma unroll
                for (int j = 0; j < 4; j++)
                    if (k0 + tc * 4 + j > q0 + tr * 4 + i) s[i][j] = -1e30f;
        }

#pragma unroll
        for (int i = 0; i < 4; i++) {
            float mt = fmaxf(fmaxf(s[i][0], s[i][1]), fmaxf(s[i][2], s[i][3]));
            mt = fmaxf(mt, __shfl_xor_sync(0xffffffffu, mt, 1));
            mt = fmaxf(mt, __shfl_xor_sync(0xffffffffu, mt, 2));
            mt = fmaxf(mt, __shfl_xor_sync(0xffffffffu, mt, 4));
            mt = fmaxf(mt, __shfl_xor_sync(0xffffffffu, mt, 8));
            float mnew  = fmaxf(m_i[i], mt);
            float alpha = __expf(m_i[i] - mnew);
            float ps = 0.f;
#pragma unroll
            for (int j = 0; j < 4; j++) {
                s[i][j] = __expf(s[i][j] - mnew);
                ps += s[i][j];
            }
            ps += __shfl_xor_sync(0xffffffffu, ps, 1);
            ps += __shfl_xor_sync(0xffffffffu, ps, 2);
            ps += __shfl_xor_sync(0xffffffffu, ps, 4);
            ps += __shfl_xor_sync(0xffffffffu, ps, 8);
            l_i[i] = l_i[i] * alpha + ps;
            m_i[i] = mnew;
#pragma unroll
            for (int c = 0; c < 8; c++) acc[i][c] *= alpha;
            Ps[tr * 4 + i][tc * 4 + 0] = s[i][0];
            Ps[tr * 4 + i][tc * 4 + 1] = s[i][1];
            Ps[tr * 4 + i][tc * 4 + 2] = s[i][2];
            Ps[tr * 4 + i][tc * 4 + 3] = s[i][3];
        }
        __syncthreads();

#pragma unroll 4
        for (int j = 0; j < 64; j++) {
            float4 v0 = *(const float4*)&Vs[j][tc * 8];
            float4 v1 = *(const float4*)&Vs[j][tc * 8 + 4];
            float p0 = Ps[tr * 4 + 0][j], p1 = Ps[tr * 4 + 1][j];
            float p2 = Ps[tr * 4 + 2][j], p3 = Ps[tr * 4 + 3][j];
            acc[0][0] += p0 * v0.x; acc[0][1] += p0 * v0.y; acc[0][2] += p0 * v0.z; acc[0][3] += p0 * v0.w;
            acc[0][4] += p0 * v1.x; acc[0][5] += p0 * v1.y; acc[0][6] += p0 * v1.z; acc[0][7] += p0 * v1.w;
            acc[1][0] += p1 * v0.x; acc[1][1] += p1 * v0.y; acc[1][2] += p1 * v0.z; acc[1][3] += p1 * v0.w;
            acc[1][4] += p1 * v1.x; acc[1][5] += p1 * v1.y; acc[1][6] += p1 * v1.z; acc[1][7] += p1 * v1.w;
            acc[2][0] += p2 * v0.x; acc[2][1] += p2 * v0.y; acc[2][2] += p2 * v0.z; acc[2][3] += p2 * v0.w;
            acc[2][4] += p2 * v1.x; acc[2][5] += p2 * v1.y; acc[2][6] += p2 * v1.z; acc[2][7] += p2 * v1.w;
            acc[3][0] += p3 * v0.x; acc[3][1] += p3 * v0.y; acc[3][2] += p3 * v0.z; acc[3][3] += p3 * v0.w;
            acc[3][4] += p3 * v1.x; acc[3][5] += p3 * v1.y; acc[3][6] += p3 * v1.z; acc[3][7] += p3 * v1.w;
        }
    }

    int b = bh >> 4, h = bh & 15;
#pragma unroll
    for (int i = 0; i < 4; i++) {
        float inv = 1.0f / l_i[i];
        int qrow = q0 + tr * 4 + i;
        float* dst = O + (size_t)(b * T_ + qrow) * D_ + h * HD_ + tc * 8;
        float4 o0 = {acc[i][0] * inv, acc[i][1] * inv, acc[i][2] * inv, acc[i][3] * inv};
        float4 o1 = {acc[i][4] * inv, acc[i][5] * inv, acc[i][6] * inv, acc[i][7] * inv};
        *(float4*)dst = o0;
        *(float4*)(dst + 4) = o1;
    }
}

// ------------------------------- launcher -----------------------------------
extern "C" void kernel_launch(void* const* d_in, const int* in_sizes, int n_in,
                              void* d_out, int out_size)
{
    const float* x      = (const float*)d_in[0];
    // d_in[1] = attn_mask (deterministic causal; applied analytically)
    const float* w_norm = (const float*)d_in[2];
    const float* wq     = (const float*)d_in[3];
    const float* wk     = (const float*)d_in[4];
    const float* wv     = (const float*)d_in[5];
    const float* wo     = (const float*)d_in[6];
    float* out = (float*)d_out;

    void *pxh, *pxl, *pwh, *pwl, *pq, *pk, *pv, *pa, *pah, *pal;
    cudaGetSymbolAddress(&pxh, g_xnh);
    cudaGetSymbolAddress(&pxl, g_xnl);
    cudaGetSymbolAddress(&pwh, g_wh);
    cudaGetSymbolAddress(&pwl, g_wl);
    cudaGetSymbolAddress(&pq,  g_q);
    cudaGetSymbolAddress(&pk,  g_k);
    cudaGetSymbolAddress(&pv,  g_v);
    cudaGetSymbolAddress(&pa,  g_attn);
    cudaGetSymbolAddress(&pah, g_ah);
    cudaGetSymbolAddress(&pal, g_al);
    __nv_bfloat16* xnh = (__nv_bfloat16*)pxh;
    __nv_bfloat16* xnl = (__nv_bfloat16*)pxl;
    __nv_bfloat16* wh  = (__nv_bfloat16*)pwh;   // 4 contiguous [D*D] blocks
    __nv_bfloat16* wl  = (__nv_bfloat16*)pwl;
    float* q    = (float*)pq;
    float* k    = (float*)pk;
    float* v    = (float*)pv;
    float* attn = (float*)pa;
    __nv_bfloat16* ah = (__nv_bfloat16*)pah;
    __nv_bfloat16* al = (__nv_bfloat16*)pal;

    cudaFuncSetAttribute(flash_kernel, cudaFuncAttributeMaxDynamicSharedMemorySize,
                         FLASH_SMEM_BYTES);
    cudaFuncSetAttribute(gemm_mma, cudaFuncAttributeMaxDynamicSharedMemorySize,
                         GEMM_SMEM);

    const size_t WSZ = (size_t)D_ * D_;
    const int wn4 = (int)(WSZ / 4);
    const float* wsrc[4] = {wq, wk, wv, wo};

    // 1) RMSNorm + split
    rmsnorm_split_kernel<<<M_, 256>>>(x, w_norm, xnh, xnl);

    // 2) split the 4 weight matrices
    for (int i = 0; i < 4; i++)
        split_kernel<<<(wn4 + 255) / 256, 256>>>(wsrc[i], wh + i * WSZ, wl + i * WSZ, wn4);

    // 3) Q/K/V projections on tensor cores (scatter to [B,H,T,HD])
    dim3 ggrid(D_ / 128, M_ / 128);
    gemm_mma<<<ggrid, 256, GEMM_SMEM>>>(xnh, xnl, wh + 0 * WSZ, wl + 0 * WSZ, q, 1);
    gemm_mma<<<ggrid, 256, GEMM_SMEM>>>(xnh, xnl, wh + 1 * WSZ, wl + 1 * WSZ, k, 1);
    gemm_mma<<<ggrid, 256, GEMM_SMEM>>>(xnh, xnl, wh + 2 * WSZ, wl + 2 * WSZ, v, 1);

    // 4) causal flash attention -> [B,T,D] fp32
    dim3 fgrid(T_ / 64, B_ * H_);
    flash_kernel<<<fgrid, 256, FLASH_SMEM_BYTES>>>(q, k, v, attn);

    // 5) split attention output, 6) output projection on tensor cores -> d_out
    split_kernel<<<((int)(M_ * (size_t)D_ / 4) + 255) / 256, 256>>>(attn, ah, al,
                                                                    (int)(M_ * (size_t)D_ / 4));
    gemm_mma<<<ggrid, 256, GEMM_SMEM>>>(ah, al, wh + 3 * WSZ, wl + 3 * WSZ, out, 0);
}

// round 8
// speedup vs baseline: 4.5874x; 1.5214x over previous
#include <cuda_runtime.h>
#include <cuda_bf16.h>
#include <cstdint>
#include <math.h>

#define B_   2
#define T_   2048
#define D_   2048
#define H_   16
#define HD_  128
#define M_   (B_ * T_)   // 4096
#define K_   2048

// ---------------- scratch (allocation-free: device globals) ----------------
__device__ __nv_bfloat16 g_xnh[(size_t)M_ * D_];
__device__ __nv_bfloat16 g_xnl[(size_t)M_ * D_];
__device__ __nv_bfloat16 g_wh [4][(size_t)D_ * D_];   // q,k,v,o
__device__ __nv_bfloat16 g_wl [4][(size_t)D_ * D_];
__device__ __nv_bfloat16 g_qh [(size_t)M_ * D_];      // [B,H,T,HD] bf16 hi/lo
__device__ __nv_bfloat16 g_ql [(size_t)M_ * D_];
__device__ __nv_bfloat16 g_kh [(size_t)M_ * D_];
__device__ __nv_bfloat16 g_kl [(size_t)M_ * D_];
__device__ __nv_bfloat16 g_vh [(size_t)M_ * D_];
__device__ __nv_bfloat16 g_vl [(size_t)M_ * D_];
__device__ __nv_bfloat16 g_ah [(size_t)M_ * D_];      // attention out [B,T,D]
__device__ __nv_bfloat16 g_al [(size_t)M_ * D_];

// ------------------------- PTX helpers (baseline sm_103 ISA) ----------------
__device__ __forceinline__ uint32_t smem_u32(const void* p) {
    uint32_t a;
    asm("{ .reg .u64 t; cvta.to.shared.u64 t, %1; cvt.u32.u64 %0, t; }" : "=r"(a) : "l"(p));
    return a;
}

#define CP_ASYNC16(dst, src) \
    asm volatile("cp.async.cg.shared.global [%0], [%1], 16;" :: "r"(dst), "l"(src))
#define CP_COMMIT() asm volatile("cp.async.commit_group;" ::: "memory")
#define CP_WAIT(n)  asm volatile("cp.async.wait_group %0;" :: "n"(n) : "memory")

#define LDSM_X4(r0, r1, r2, r3, a) \
    asm volatile("ldmatrix.sync.aligned.m8n8.x4.shared.b16 {%0,%1,%2,%3}, [%4];" \
                 : "=r"(r0), "=r"(r1), "=r"(r2), "=r"(r3) : "r"(a))

#define MMA16816(d, a0, a1, a2, a3, b0, b1) \
    asm volatile("mma.sync.aligned.m16n8k16.row.col.f32.bf16.bf16.f32 " \
                 "{%0,%1,%2,%3}, {%4,%5,%6,%7}, {%8,%9}, {%0,%1,%2,%3};" \
                 : "+f"((d)[0]), "+f"((d)[1]), "+f"((d)[2]), "+f"((d)[3]) \
                 : "r"(a0), "r"(a1), "r"(a2), "r"(a3), "r"(b0), "r"(b1))

__device__ __forceinline__ uint32_t u4_get(const uint4& v, int j) {
    uint32_t w = ((j >> 1) == 0) ? v.x : ((j >> 1) == 1) ? v.y : ((j >> 1) == 2) ? v.z : v.w;
    return (j & 1) ? (w >> 16) : (w & 0xffffu);
}

// ---------------------- RMSNorm + split to bf16 hi/lo -----------------------
__global__ __launch_bounds__(256) void rmsnorm_split_kernel(const float* __restrict__ x,
                                                            const float* __restrict__ w,
                                                            __nv_bfloat16* __restrict__ hi,
                                                            __nv_bfloat16* __restrict__ lo)
{
    int row = blockIdx.x;
    const float* xr = x + (size_t)row * D_;
    int tid = threadIdx.x;

    float s = 0.f;
#pragma unroll
    for (int c = tid * 4; c < D_; c += 256 * 4) {
        float4 v = *(const float4*)(xr + c);
        s += v.x * v.x + v.y * v.y + v.z * v.z + v.w * v.w;
    }
#pragma unroll
    for (int m = 16; m; m >>= 1) s += __shfl_xor_sync(0xffffffffu, s, m);

    __shared__ float red[8];
    __shared__ float totsh;
    if ((tid & 31) == 0) red[tid >> 5] = s;
    __syncthreads();
    if (tid == 0) {
        float t = 0.f;
#pragma unroll
        for (int i = 0; i < 8; i++) t += red[i];
        totsh = t;
    }
    __syncthreads();

    float norm = sqrtf(totsh) * 0.022097086912079608f;  // * D^-0.5
    float inv  = 1.0f / (norm + 1e-8f);

#pragma unroll
    for (int c = tid * 4; c < D_; c += 256 * 4) {
        float4 v  = *(const float4*)(xr + c);
        float4 wv = *(const float4*)(w + c);
        float o[4] = {wv.x * v.x * inv, wv.y * v.y * inv, wv.z * v.z * inv, wv.w * v.w * inv};
#pragma unroll
        for (int j = 0; j < 4; j++) {
            __nv_bfloat16 h = __float2bfloat16_rn(o[j]);
            float r = o[j] - __bfloat162float(h);
            hi[(size_t)row * D_ + c + j] = h;
            lo[(size_t)row * D_ + c + j] = __float2bfloat16_rn(r);
        }
    }
}

// -------------------------- fp32 -> bf16 hi/lo split (weights) --------------
__global__ __launch_bounds__(256) void split_kernel(const float* __restrict__ x,
                                                    __nv_bfloat16* __restrict__ hi,
                                                    __nv_bfloat16* __restrict__ lo,
                                                    int n4)
{
    int i = blockIdx.x * 256 + threadIdx.x;
    if (i >= n4) return;
    float4 v = ((const float4*)x)[i];
    float a[4] = {v.x, v.y, v.z, v.w};
    __nv_bfloat16 h[4], l[4];
#pragma unroll
    for (int j = 0; j < 4; j++) {
        h[j] = __float2bfloat16_rn(a[j]);
        l[j] = __float2bfloat16_rn(a[j] - __bfloat162float(h[j]));
    }
    ((__nv_bfloat162*)hi)[i * 2 + 0] = __nv_bfloat162(h[0], h[1]);
    ((__nv_bfloat162*)hi)[i * 2 + 1] = __nv_bfloat162(h[2], h[3]);
    ((__nv_bfloat162*)lo)[i * 2 + 0] = __nv_bfloat162(l[0], l[1]);
    ((__nv_bfloat162*)lo)[i * 2 + 1] = __nv_bfloat162(l[2], l[3]);
}

// ------ warp-MMA GEMM: C[M,N] = (Ah+Al)[M,K] @ (Bh+Bl)[N,K]^T  (bf16x3) -----
#define SROW     80
#define TILE_B   (128 * SROW)
#define STAGE_B  (4 * TILE_B)
#define GEMM_SMEM (2 * STAGE_B)

__device__ __forceinline__ void gemm_issue_loads(uint32_t sb, int stage,
                                                 const __nv_bfloat16* Ah,
                                                 const __nv_bfloat16* Al,
                                                 const __nv_bfloat16* Bh,
                                                 const __nv_bfloat16* Bl,
                                                 int m0, int n0, int k0, int tid)
{
    const __nv_bfloat16* srcs[4] = {Ah, Al, Bh, Bl};
    uint32_t base = sb + stage * STAGE_B;
#pragma unroll
    for (int it = 0; it < 8; ++it) {
        int i = tid + it * 256;
        int tile = i >> 9;
        int j = i & 511;
        int r = j >> 2, cv = j & 3;
        int row0 = (tile < 2) ? m0 : n0;
        const __nv_bfloat16* src = srcs[tile] + (size_t)(row0 + r) * K_ + k0 + cv * 8;
        CP_ASYNC16(base + tile * TILE_B + r * SROW + cv * 16, src);
    }
}

// epi=1: scatter to [B,H,T,HD] as bf16 hi/lo with fp32 scale folded pre-split.
// epi=0: plain fp32 row-major [M,N] into Cf.
__global__ __launch_bounds__(256, 2) void gemm_mma(const __nv_bfloat16* __restrict__ Ah,
                                                   const __nv_bfloat16* __restrict__ Al,
                                                   const __nv_bfloat16* __restrict__ Bh,
                                                   const __nv_bfloat16* __restrict__ Bl,
                                                   float* __restrict__ Cf,
                                                   __nv_bfloat16* __restrict__ Ch,
                                                   __nv_bfloat16* __restrict__ Cl,
                                                   int epi, float scale)
{
    extern __shared__ char smem[];
    uint32_t sb = smem_u32(smem);
    int tid = threadIdx.x, wid = tid >> 5, lane = tid & 31;
    int m0 = blockIdx.y * 128, n0 = blockIdx.x * 128;
    int warpM = wid & 1, warpN = wid >> 1;

    float acc[4][4][4];
#pragma unroll
    for (int i = 0; i < 4; i++)
#pragma unroll
        for (int j = 0; j < 4; j++)
#pragma unroll
            for (int c = 0; c < 4; c++) acc[i][j][c] = 0.f;

    int aRow = warpM * 64 + (lane & 15);
    int aColHalf = (lane >> 4) * 8;
    int bMat = lane >> 3;
    int bRow = warpN * 32 + (bMat >> 1) * 8 + (lane & 7);
    int bColHalf = (bMat & 1) * 8;

    const int NCHUNK = K_ / 32;

    gemm_issue_loads(sb, 0, Ah, Al, Bh, Bl, m0, n0, 0, tid);
    CP_COMMIT();

    for (int c = 0; c < NCHUNK; ++c) {
        if (c + 1 < NCHUNK) {
            gemm_issue_loads(sb, (c + 1) & 1, Ah, Al, Bh, Bl, m0, n0, (c + 1) * 32, tid);
            CP_COMMIT();
            CP_WAIT(1);
        } else {
            CP_WAIT(0);
        }
        __syncthreads();

        uint32_t st = sb + (c & 1) * STAGE_B;
        uint32_t tAh = st, tAl = st + TILE_B, tBh = st + 2 * TILE_B, tBl = st + 3 * TILE_B;

#pragma unroll
        for (int kk = 0; kk < 32; kk += 16) {
            uint32_t a[4][4], bh[4][2], bl[4][2];
#pragma unroll
            for (int fm = 0; fm < 4; fm++) {
                uint32_t ad = tAh + (aRow + fm * 16) * SROW + (kk + aColHalf) * 2;
                LDSM_X4(a[fm][0], a[fm][1], a[fm][2], a[fm][3], ad);
            }
#pragma unroll
            for (int g = 0; g < 2; g++) {
                uint32_t bd = tBh + (bRow + g * 16) * SROW + (kk + bColHalf) * 2;
                LDSM_X4(bh[2 * g][0], bh[2 * g][1], bh[2 * g + 1][0], bh[2 * g + 1][1], bd);
                uint32_t bd2 = tBl + (bRow + g * 16) * SROW + (kk + bColHalf) * 2;
                LDSM_X4(bl[2 * g][0], bl[2 * g][1], bl[2 * g + 1][0], bl[2 * g + 1][1], bd2);
            }
#pragma unroll
            for (int fm = 0; fm < 4; fm++)
#pragma unroll
                for (int fn = 0; fn < 4; fn++)
                    MMA16816(acc[fm][fn], a[fm][0], a[fm][1], a[fm][2], a[fm][3],
                             bh[fn][0], bh[fn][1]);
#pragma unroll
            for (int fm = 0; fm < 4; fm++)
#pragma unroll
                for (int fn = 0; fn < 4; fn++)
                    MMA16816(acc[fm][fn], a[fm][0], a[fm][1], a[fm][2], a[fm][3],
                             bl[fn][0], bl[fn][1]);
#pragma unroll
            for (int fm = 0; fm < 4; fm++) {
                uint32_t ad = tAl + (aRow + fm * 16) * SROW + (kk + aColHalf) * 2;
                LDSM_X4(a[fm][0], a[fm][1], a[fm][2], a[fm][3], ad);
            }
#pragma unroll
            for (int fm = 0; fm < 4; fm++)
#pragma unroll
                for (int fn = 0; fn < 4; fn++)
                    MMA16816(acc[fm][fn], a[fm][0], a[fm][1], a[fm][2], a[fm][3],
                             bh[fn][0], bh[fn][1]);
        }
        __syncthreads();
    }

#pragma unroll
    for (int fm = 0; fm < 4; fm++) {
#pragma unroll
        for (int fn = 0; fn < 4; fn++) {
            int m = m0 + warpM * 64 + fm * 16 + (lane >> 2);
            int n = n0 + warpN * 32 + fn * 8 + (lane & 3) * 2;
#pragma unroll
            for (int half = 0; half < 2; half++) {
                int mr = m + half * 8;
                float v0 = acc[fm][fn][half * 2] * scale;
                float v1 = acc[fm][fn][half * 2 + 1] * scale;
                if (epi) {
                    int b = mr >> 11, t = mr & (T_ - 1);
                    int hhd = n >> 7, hd = n & (HD_ - 1);
                    size_t off = (((size_t)((b * H_ + hhd) * T_ + t)) << 7) + hd;
                    __nv_bfloat16 h0 = __float2bfloat16_rn(v0);
                    __nv_bfloat16 h1 = __float2bfloat16_rn(v1);
                    *(__nv_bfloat162*)(Ch + off) = __nv_bfloat162(h0, h1);
                    __nv_bfloat16 l0 = __float2bfloat16_rn(v0 - __bfloat162float(h0));
                    __nv_bfloat16 l1 = __float2bfloat16_rn(v1 - __bfloat162float(h1));
                    *(__nv_bfloat162*)(Cl + off) = __nv_bfloat162(l0, l1);
                } else {
                    float2 o = {v0, v1};
                    *(float2*)(Cf + (size_t)mr * D_ + n) = o;
                }
            }
        }
    }
}

// -------------------- Flash attention (causal, tensor cores) ----------------
// Br=128, Bc=64, 8 warps. bf16x3 for both QK^T and P@V.
// smem (bytes): Qh 0, Ql 34816, Kbuf 69632 (2 stages x 34816; Kl at +17408),
// Vt hi 139264, Vt lo 157696 (128 rows x 144B, [hd][token]),
// Ph 176128, Pl 194560 (128 rows x 144B). Total 212992.
#define FL_QH  0
#define FL_QL  34816
#define FL_K0  69632
#define FL_VTH 139264
#define FL_VTL 157696
#define FL_PH  176128
#define FL_PL  194560
#define FLASH_SMEM 212992

__global__ __launch_bounds__(256, 1) void flash_mma(
    const __nv_bfloat16* __restrict__ Qh, const __nv_bfloat16* __restrict__ Ql,
    const __nv_bfloat16* __restrict__ Kh, const __nv_bfloat16* __restrict__ Kl,
    const __nv_bfloat16* __restrict__ Vh, const __nv_bfloat16* __restrict__ Vl,
    __nv_bfloat16* __restrict__ Oh, __nv_bfloat16* __restrict__ Ol)
{
    extern __shared__ char smem[];
    uint32_t sb = smem_u32(smem);
    int tid = threadIdx.x, wid = tid >> 5, lane = tid & 31;
    int qt = blockIdx.x, bh = blockIdx.y;
    int q0 = qt * 128;
    size_t hbase = (size_t)bh * T_ * HD_;
    const __nv_bfloat16 *Qhp = Qh + hbase + (size_t)q0 * HD_;
    const __nv_bfloat16 *Qlp = Ql + hbase + (size_t)q0 * HD_;
    const __nv_bfloat16 *Khp = Kh + hbase, *Klp = Kl + hbase;
    const __nv_bfloat16 *Vhp = Vh + hbase, *Vlp = Vl + hbase;

    // Q tiles -> smem (async), rows padded to 272B
#pragma unroll
    for (int it = 0; it < 16; ++it) {
        int i = tid + it * 256;
        int hl = i >> 11, j = i & 2047;
        int r = j >> 4, c16 = j & 15;
        const __nv_bfloat16* src = (hl ? Qlp : Qhp) + (size_t)r * HD_ + c16 * 8;
        CP_ASYNC16(sb + (hl ? FL_QL : FL_QH) + r * 272 + c16 * 16, src);
    }
    CP_COMMIT();

    // K tile 0 -> smem stage 0
#pragma unroll
    for (int it = 0; it < 8; ++it) {
        int i = tid + it * 256;
        int hl = i >> 10, j = i & 1023;
        int r = j >> 4, c16 = j & 15;
        const __nv_bfloat16* src = (hl ? Klp : Khp) + (size_t)r * HD_ + c16 * 8;
        CP_ASYNC16(sb + FL_K0 + hl * 17408 + r * 272 + c16 * 16, src);
    }
    CP_COMMIT();

    // V tile 0 -> regs (thread: tokens 2*lane,2*lane+1; hd blocks wid*8, wid*8+64)
    uint4 vha0, vhb0, vha1, vhb1, vla0, vlb0, vla1, vlb1;
    {
        const __nv_bfloat16* s0 = Vhp + (size_t)(2 * lane) * HD_ + wid * 8;
        vha0 = *(const uint4*)(s0);
        vhb0 = *(const uint4*)(s0 + HD_);
        vha1 = *(const uint4*)(s0 + 64);
        vhb1 = *(const uint4*)(s0 + HD_ + 64);
        const __nv_bfloat16* s1 = Vlp + (size_t)(2 * lane) * HD_ + wid * 8;
        vla0 = *(const uint4*)(s1);
        vlb0 = *(const uint4*)(s1 + HD_);
        vla1 = *(const uint4*)(s1 + 64);
        vlb1 = *(const uint4*)(s1 + HD_ + 64);
    }

    float m_i[2] = {-1e30f, -1e30f}, l_i[2] = {0.f, 0.f};
    float o[16][4];
#pragma unroll
    for (int i = 0; i < 16; i++)
#pragma unroll
        for (int c = 0; c < 4; c++) o[i][c] = 0.f;

    const int aRow = lane & 15, aColH = (lane >> 4) * 8;
    const int bMat = lane >> 3;
    const int bRowB = ((bMat >> 1) * 8) + (lane & 7);
    const int bColH = (bMat & 1) * 8;
    int nkt = 2 * qt + 2;

    for (int kt = 0; kt < nkt; ++kt) {
        __syncthreads();          // all reads of Vt/Kbuf[(kt+1)&1] from prior iters done
        CP_WAIT(0);               // K(kt) (and Q on iter 0) arrived

        // transpose-store V tile kt -> Vt smem [hd][token]
#pragma unroll
        for (int j = 0; j < 8; j++) {
            *(uint32_t*)(smem + FL_VTH + (wid * 8 + j) * 144 + lane * 4) =
                u4_get(vha0, j) | (u4_get(vhb0, j) << 16);
            *(uint32_t*)(smem + FL_VTH + (64 + wid * 8 + j) * 144 + lane * 4) =
                u4_get(vha1, j) | (u4_get(vhb1, j) << 16);
            *(uint32_t*)(smem + FL_VTL + (wid * 8 + j) * 144 + lane * 4) =
                u4_get(vla0, j) | (u4_get(vlb0, j) << 16);
            *(uint32_t*)(smem + FL_VTL + (64 + wid * 8 + j) * 144 + lane * 4) =
                u4_get(vla1, j) | (u4_get(vlb1, j) << 16);
        }

        // prefetch K(kt+1) via cp.async and V(kt+1) into regs
        if (kt + 1 < nkt) {
            int k0n = (kt + 1) * 64;
#pragma unroll
            for (int it = 0; it < 8; ++it) {
                int i = tid + it * 256;
                int hl = i >> 10, j = i & 1023;
                int r = j >> 4, c16 = j & 15;
                const __nv_bfloat16* src = (hl ? Klp : Khp) + (size_t)(k0n + r) * HD_ + c16 * 8;
                CP_ASYNC16(sb + FL_K0 + ((kt + 1) & 1) * 34816 + hl * 17408 + r * 272 + c16 * 16,
                           src);
            }
            CP_COMMIT();
            const __nv_bfloat16* s0 = Vhp + (size_t)(k0n + 2 * lane) * HD_ + wid * 8;
            vha0 = *(const uint4*)(s0);
            vhb0 = *(const uint4*)(s0 + HD_);
            vha1 = *(const uint4*)(s0 + 64);
            vhb1 = *(const uint4*)(s0 + HD_ + 64);
            const __nv_bfloat16* s1 = Vlp + (size_t)(k0n + 2 * lane) * HD_ + wid * 8;
            vla0 = *(const uint4*)(s1);
            vlb0 = *(const uint4*)(s1 + HD_);
            vla1 = *(const uint4*)(s1 + 64);
            vlb1 = *(const uint4*)(s1 + HD_ + 64);
        }
        __syncthreads();          // Vt visible to all warps

        // ---- S = Q @ K^T (bf16x3), warp computes m16 x n64 over k128 -------
        uint32_t kb = sb + FL_K0 + (kt & 1) * 34816;
        float sc[8][4];
#pragma unroll
        for (int i = 0; i < 8; i++)
#pragma unroll
            for (int c = 0; c < 4; c++) sc[i][c] = 0.f;

        uint32_t qha = sb + FL_QH + (wid * 16 + aRow) * 272 + aColH * 2;
        uint32_t qla = sb + FL_QL + (wid * 16 + aRow) * 272 + aColH * 2;
#pragma unroll
        for (int ks = 0; ks < 8; ++ks) {
            uint32_t a0, a1, a2, a3, e0, e1, e2, e3;
            LDSM_X4(a0, a1, a2, a3, qha + ks * 32);
            LDSM_X4(e0, e1, e2, e3, qla + ks * 32);
#pragma unroll
            for (int nf2 = 0; nf2 < 4; ++nf2) {
                uint32_t badr = kb + (nf2 * 16 + bRowB) * 272 + (ks * 16 + bColH) * 2;
                uint32_t b0, b1, b2, b3, c0, c1, c2, c3;
                LDSM_X4(b0, b1, b2, b3, badr);
                LDSM_X4(c0, c1, c2, c3, badr + 17408);
                MMA16816(sc[nf2 * 2 + 0], a0, a1, a2, a3, b0, b1);
                MMA16816(sc[nf2 * 2 + 1], a0, a1, a2, a3, b2, b3);
                MMA16816(sc[nf2 * 2 + 0], a0, a1, a2, a3, c0, c1);
                MMA16816(sc[nf2 * 2 + 1], a0, a1, a2, a3, c2, c3);
                MMA16816(sc[nf2 * 2 + 0], e0, e1, e2, e3, b0, b1);
                MMA16816(sc[nf2 * 2 + 1], e0, e1, e2, e3, b2, b3);
            }
        }

        // causal mask (diagonal-region tiles only)
        if (kt >= 2 * qt) {
            int r0 = q0 + wid * 16 + (lane >> 2);
            int cb = kt * 64 + (lane & 3) * 2;
#pragma unroll
            for (int nf = 0; nf < 8; ++nf)
#pragma unroll
                for (int c = 0; c < 4; ++c) {
                    int row = r0 + ((c >> 1) << 3);
                    int col = cb + nf * 8 + (c & 1);
                    if (col > row) sc[nf][c] = -1e30f;
                }
        }

        // ---- online softmax (2 rows per thread; quad = lanes sharing rows) -
        float mt0 = -1e30f, mt1 = -1e30f;
#pragma unroll
        for (int nf = 0; nf < 8; ++nf) {
            mt0 = fmaxf(mt0, fmaxf(sc[nf][0], sc[nf][1]));
            mt1 = fmaxf(mt1, fmaxf(sc[nf][2], sc[nf][3]));
        }
        mt0 = fmaxf(mt0, __shfl_xor_sync(0xffffffffu, mt0, 1));
        mt0 = fmaxf(mt0, __shfl_xor_sync(0xffffffffu, mt0, 2));
        mt1 = fmaxf(mt1, __shfl_xor_sync(0xffffffffu, mt1, 1));
        mt1 = fmaxf(mt1, __shfl_xor_sync(0xffffffffu, mt1, 2));
        float mn0 = fmaxf(m_i[0], mt0), mn1 = fmaxf(m_i[1], mt1);
        float al0 = __expf(m_i[0] - mn0), al1 = __expf(m_i[1] - mn1);
        float ps0 = 0.f, ps1 = 0.f;
#pragma unroll
        for (int nf = 0; nf < 8; ++nf) {
            sc[nf][0] = __expf(sc[nf][0] - mn0); ps0 += sc[nf][0];
            sc[nf][1] = __expf(sc[nf][1] - mn0); ps0 += sc[nf][1];
            sc[nf][2] = __expf(sc[nf][2] - mn1); ps1 += sc[nf][2];
            sc[nf][3] = __expf(sc[nf][3] - mn1); ps1 += sc[nf][3];
        }
        ps0 += __shfl_xor_sync(0xffffffffu, ps0, 1);
        ps0 += __shfl_xor_sync(0xffffffffu, ps0, 2);
        ps1 += __shfl_xor_sync(0xffffffffu, ps1, 1);
        ps1 += __shfl_xor_sync(0xffffffffu, ps1, 2);
        l_i[0] = l_i[0] * al0 + ps0;  m_i[0] = mn0;
        l_i[1] = l_i[1] * al1 + ps1;  m_i[1] = mn1;
#pragma unroll
        for (int nf = 0; nf < 16; ++nf) {
            o[nf][0] *= al0; o[nf][1] *= al0;
            o[nf][2] *= al1; o[nf][3] *= al1;
        }

        // write P hi/lo to smem (own 16 rows only)
#pragma unroll
        for (int h = 0; h < 2; ++h) {
            int prow = wid * 16 + (lane >> 2) + 8 * h;
            int pcol = (lane & 3) * 2;
#pragma unroll
            for (int nf = 0; nf < 8; ++nf) {
                float p0 = sc[nf][2 * h], p1 = sc[nf][2 * h + 1];
                __nv_bfloat16 h0 = __float2bfloat16_rn(p0);
                __nv_bfloat16 h1 = __float2bfloat16_rn(p1);
                *(__nv_bfloat162*)(smem + FL_PH + prow * 144 + (nf * 8 + pcol) * 2) =
                    __nv_bfloat162(h0, h1);
                __nv_bfloat16 l0 = __float2bfloat16_rn(p0 - __bfloat162float(h0));
                __nv_bfloat16 l1 = __float2bfloat16_rn(p1 - __bfloat162float(h1));
                *(__nv_bfloat162*)(smem + FL_PL + prow * 144 + (nf * 8 + pcol) * 2) =
                    __nv_bfloat162(l0, l1);
            }
        }
        __syncwarp();

        // ---- O += P @ V (bf16x3), m16 x n128 over k64 ----------------------
        uint32_t pha = sb + FL_PH + (wid * 16 + aRow) * 144 + aColH * 2;
        uint32_t pla = sb + FL_PL + (wid * 16 + aRow) * 144 + aColH * 2;
#pragma unroll
        for (int ks = 0; ks < 4; ++ks) {
            uint32_t a0, a1, a2, a3, e0, e1, e2, e3;
            LDSM_X4(a0, a1, a2, a3, pha + ks * 32);
            LDSM_X4(e0, e1, e2, e3, pla + ks * 32);
#pragma unroll
            for (int nf2 = 0; nf2 < 8; ++nf2) {
                uint32_t vadr = sb + FL_VTH + (nf2 * 16 + bRowB) * 144 + (ks * 16 + bColH) * 2;
                uint32_t b0, b1, b2, b3, c0, c1, c2, c3;
                LDSM_X4(b0, b1, b2, b3, vadr);
                LDSM_X4(c0, c1, c2, c3, vadr + 18432);
                MMA16816(o[nf2 * 2 + 0], a0, a1, a2, a3, b0, b1);
                MMA16816(o[nf2 * 2 + 1], a0, a1, a2, a3, b2, b3);
                MMA16816(o[nf2 * 2 + 0], a0, a1, a2, a3, c0, c1);
                MMA16816(o[nf2 * 2 + 1], a0, a1, a2, a3, c2, c3);
                MMA16816(o[nf2 * 2 + 0], e0, e1, e2, e3, b0, b1);
                MMA16816(o[nf2 * 2 + 1], e0, e1, e2, e3, b2, b3);
            }
        }
    }

    // epilogue: O /= l, write bf16 hi/lo to [B,T,D]
    int bb = bh >> 4, hh = bh & 15;
    float inv[2] = {1.f / l_i[0], 1.f / l_i[1]};
#pragma unroll
    for (int h = 0; h < 2; ++h) {
        int row = q0 + wid * 16 + (lane >> 2) + 8 * h;
        size_t rb = (size_t)(bb * T_ + row) * D_ + hh * HD_ + (lane & 3) * 2;
#pragma unroll
        for (int nf = 0; nf < 16; ++nf) {
            float v0 = o[nf][2 * h] * inv[h], v1 = o[nf][2 * h + 1] * inv[h];
            __nv_bfloat16 h0 = __float2bfloat16_rn(v0), h1 = __float2bfloat16_rn(v1);
            *(__nv_bfloat162*)(Oh + rb + nf * 8) = __nv_bfloat162(h0, h1);
            __nv_bfloat16 L0 = __float2bfloat16_rn(v0 - __bfloat162float(h0));
            __nv_bfloat16 L1 = __float2bfloat16_rn(v1 - __bfloat162float(h1));
            *(__nv_bfloat162*)(Ol + rb + nf * 8) = __nv_bfloat162(L0, L1);
        }
    }
}

// ------------------------------- launcher -----------------------------------
extern "C" void kernel_launch(void* const* d_in, const int* in_sizes, int n_in,
                              void* d_out, int out_size)
{
    const float* x      = (const float*)d_in[0];
    // d_in[1] = attn_mask (deterministic causal; applied analytically)
    const float* w_norm = (const float*)d_in[2];
    const float* wq     = (const float*)d_in[3];
    const float* wk     = (const float*)d_in[4];
    const float* wv     = (const float*)d_in[5];
    const float* wo     = (const float*)d_in[6];
    float* out = (float*)d_out;

    void *pxh, *pxl, *pwh, *pwl, *pqh, *pql, *pkh, *pkl, *pvh, *pvl, *pah, *pal;
    cudaGetSymbolAddress(&pxh, g_xnh);
    cudaGetSymbolAddress(&pxl, g_xnl);
    cudaGetSymbolAddress(&pwh, g_wh);
    cudaGetSymbolAddress(&pwl, g_wl);
    cudaGetSymbolAddress(&pqh, g_qh);
    cudaGetSymbolAddress(&pql, g_ql);
    cudaGetSymbolAddress(&pkh, g_kh);
    cudaGetSymbolAddress(&pkl, g_kl);
    cudaGetSymbolAddress(&pvh, g_vh);
    cudaGetSymbolAddress(&pvl, g_vl);
    cudaGetSymbolAddress(&pah, g_ah);
    cudaGetSymbolAddress(&pal, g_al);
    __nv_bfloat16* xnh = (__nv_bfloat16*)pxh;
    __nv_bfloat16* xnl = (__nv_bfloat16*)pxl;
    __nv_bfloat16* wh  = (__nv_bfloat16*)pwh;
    __nv_bfloat16* wl  = (__nv_bfloat16*)pwl;
    __nv_bfloat16* qh  = (__nv_bfloat16*)pqh;
    __nv_bfloat16* ql  = (__nv_bfloat16*)pql;
    __nv_bfloat16* kh  = (__nv_bfloat16*)pkh;
    __nv_bfloat16* kl  = (__nv_bfloat16*)pkl;
    __nv_bfloat16* vh  = (__nv_bfloat16*)pvh;
    __nv_bfloat16* vl  = (__nv_bfloat16*)pvl;
    __nv_bfloat16* ah  = (__nv_bfloat16*)pah;
    __nv_bfloat16* al  = (__nv_bfloat16*)pal;

    cudaFuncSetAttribute(gemm_mma, cudaFuncAttributeMaxDynamicSharedMemorySize, GEMM_SMEM);
    cudaFuncSetAttribute(flash_mma, cudaFuncAttributeMaxDynamicSharedMemorySize, FLASH_SMEM);

    const size_t WSZ = (size_t)D_ * D_;
    const int wn4 = (int)(WSZ / 4);
    const float* wsrc[4] = {wq, wk, wv, wo};

    // 1) RMSNorm + split
    rmsnorm_split_kernel<<<M_, 256>>>(x, w_norm, xnh, xnl);

    // 2) split the 4 weight matrices
    for (int i = 0; i < 4; i++)
        split_kernel<<<(wn4 + 255) / 256, 256>>>(wsrc[i], wh + i * WSZ, wl + i * WSZ, wn4);

    // 3) Q/K/V projections -> bf16 hi/lo [B,H,T,HD]; HD^-0.5 folded into Q
    dim3 ggrid(D_ / 128, M_ / 128);
    gemm_mma<<<ggrid, 256, GEMM_SMEM>>>(xnh, xnl, wh + 0 * WSZ, wl + 0 * WSZ,
                                        nullptr, qh, ql, 1, 0.08838834764831845f);
    gemm_mma<<<ggrid, 256, GEMM_SMEM>>>(xnh, xnl, wh + 1 * WSZ, wl + 1 * WSZ,
                                        nullptr, kh, kl, 1, 1.0f);
    gemm_mma<<<ggrid, 256, GEMM_SMEM>>>(xnh, xnl, wh + 2 * WSZ, wl + 2 * WSZ,
                                        nullptr, vh, vl, 1, 1.0f);

    // 4) causal flash attention on tensor cores -> bf16 hi/lo [B,T,D]
    dim3 fgrid(T_ / 128, B_ * H_);
    flash_mma<<<fgrid, 256, FLASH_SMEM>>>(qh, ql, kh, kl, vh, vl, ah, al);

    // 5) output projection -> d_out (fp32)
    gemm_mma<<<ggrid, 256, GEMM_SMEM>>>(ah, al, wh + 3 * WSZ, wl + 3 * WSZ,
                                        out, nullptr, nullptr, 0, 1.0f);
}

// round 13
// speedup vs baseline: 6.7229x; 1.4655x over previous
#include <cuda_runtime.h>
#include <cuda_fp16.h>
#include <cstdint>
#include <math.h>

#define B_   2
#define T_   2048
#define D_   2048
#define H_   16
#define HD_  128
#define M_   (B_ * T_)   // 4096
#define K_   2048

// ---------------- scratch (allocation-free: device globals) ----------------
__device__ __half g_xnh[(size_t)M_ * D_];
__device__ __half g_xnl[(size_t)M_ * D_];
__device__ __half g_wh [4][(size_t)D_ * D_];   // q,k,v,o (fp16 single)
__device__ __half g_qh [(size_t)M_ * D_];      // [B,H,T,HD] fp16 hi/lo
__device__ __half g_ql [(size_t)M_ * D_];
__device__ __half g_kh [(size_t)M_ * D_];
__device__ __half g_kl [(size_t)M_ * D_];
__device__ __half g_vh [(size_t)M_ * D_];      // V: hi only
__device__ __half g_ah [(size_t)M_ * D_];      // attention out [B,T,D] hi/lo
__device__ __half g_al [(size_t)M_ * D_];

// ------------------------- PTX helpers (baseline sm_103 ISA) ----------------
__device__ __forceinline__ uint32_t smem_u32(const void* p) {
    uint32_t a;
    asm("{ .reg .u64 t; cvta.to.shared.u64 t, %1; cvt.u32.u64 %0, t; }" : "=r"(a) : "l"(p));
    return a;
}

#define CP_ASYNC16(dst, src) \
    asm volatile("cp.async.cg.shared.global [%0], [%1], 16;" :: "r"(dst), "l"(src))
#define CP_COMMIT() asm volatile("cp.async.commit_group;" ::: "memory")
#define CP_WAIT(n)  asm volatile("cp.async.wait_group %0;" :: "n"(n) : "memory")

#define LDSM_X4(r0, r1, r2, r3, a) \
    asm volatile("ldmatrix.sync.aligned.m8n8.x4.shared.b16 {%0,%1,%2,%3}, [%4];" \
                 : "=r"(r0), "=r"(r1), "=r"(r2), "=r"(r3) : "r"(a))

#define MMA16816(d, a0, a1, a2, a3, b0, b1) \
    asm volatile("mma.sync.aligned.m16n8k16.row.col.f32.f16.f16.f32 " \
                 "{%0,%1,%2,%3}, {%4,%5,%6,%7}, {%8,%9}, {%0,%1,%2,%3};" \
                 : "+f"((d)[0]), "+f"((d)[1]), "+f"((d)[2]), "+f"((d)[3]) \
                 : "r"(a0), "r"(a1), "r"(a2), "r"(a3), "r"(b0), "r"(b1))

__device__ __forceinline__ uint32_t u4_get(const uint4& v, int j) {
    uint32_t w = ((j >> 1) == 0) ? v.x : ((j >> 1) == 1) ? v.y : ((j >> 1) == 2) ? v.z : v.w;
    return (j & 1) ? (w >> 16) : (w & 0xffffu);
}

// ---------------------- RMSNorm + split to fp16 hi/lo -----------------------
__global__ __launch_bounds__(256) void rmsnorm_split_kernel(const float* __restrict__ x,
                                                            const float* __restrict__ w,
                                                            __half* __restrict__ hi,
                                                            __half* __restrict__ lo)
{
    int row = blockIdx.x;
    const float* xr = x + (size_t)row * D_;
    int tid = threadIdx.x;

    float s = 0.f;
#pragma unroll
    for (int c = tid * 4; c < D_; c += 256 * 4) {
        float4 v = *(const float4*)(xr + c);
        s += v.x * v.x + v.y * v.y + v.z * v.z + v.w * v.w;
    }
#pragma unroll
    for (int m = 16; m; m >>= 1) s += __shfl_xor_sync(0xffffffffu, s, m);

    __shared__ float red[8];
    __shared__ float totsh;
    if ((tid & 31) == 0) red[tid >> 5] = s;
    __syncthreads();
    if (tid == 0) {
        float t = 0.f;
#pragma unroll
        for (int i = 0; i < 8; i++) t += red[i];
        totsh = t;
    }
    __syncthreads();

    float norm = sqrtf(totsh) * 0.022097086912079608f;  // * D^-0.5
    float inv  = 1.0f / (norm + 1e-8f);

#pragma unroll
    for (int c = tid * 4; c < D_; c += 256 * 4) {
        float4 v  = *(const float4*)(xr + c);
        float4 wv = *(const float4*)(w + c);
        float o[4] = {wv.x * v.x * inv, wv.y * v.y * inv, wv.z * v.z * inv, wv.w * v.w * inv};
#pragma unroll
        for (int j = 0; j < 4; j++) {
            __half h = __float2half_rn(o[j]);
            float r = o[j] - __half2float(h);
            hi[(size_t)row * D_ + c + j] = h;
            lo[(size_t)row * D_ + c + j] = __float2half_rn(r);
        }
    }
}

// -------------------------- fp32 -> fp16 convert (weights) ------------------
__global__ __launch_bounds__(256) void convert_kernel(const float* __restrict__ x,
                                                      __half* __restrict__ hi,
                                                      int n4)
{
    int i = blockIdx.x * 256 + threadIdx.x;
    if (i >= n4) return;
    float4 v = ((const float4*)x)[i];
    __half2 p0 = __halves2half2(__float2half_rn(v.x), __float2half_rn(v.y));
    __half2 p1 = __halves2half2(__float2half_rn(v.z), __float2half_rn(v.w));
    ((__half2*)hi)[i * 2 + 0] = p0;
    ((__half2*)hi)[i * 2 + 1] = p1;
}

// ------ warp-MMA GEMM core: acc = (Ah+Al)[M,K] @ Bh[N,K]^T  (fp16, 2-pass) --
#define SROW     80
#define TILE_B   (128 * SROW)            // 10240
#define STAGE_B  (3 * TILE_B)            // Ah, Al, Bh
#define GEMM_SMEM (2 * STAGE_B)          // 61440

__device__ __forceinline__ void gemm_issue_loads(uint32_t sb, int stage,
                                                 const __half* Ah, const __half* Al,
                                                 const __half* Bh,
                                                 int m0, int n0, int k0, int tid)
{
    const __half* srcs[3] = {Ah, Al, Bh};
    uint32_t base = sb + stage * STAGE_B;
#pragma unroll
    for (int it = 0; it < 6; ++it) {
        int i = tid + it * 256;          // 0..1535
        int tile = i >> 9;               // 0..2
        int j = i & 511;
        int r = j >> 2, cv = j & 3;
        int row0 = (tile < 2) ? m0 : n0;
        const __half* src = srcs[tile] + (size_t)(row0 + r) * K_ + k0 + cv * 8;
        CP_ASYNC16(base + tile * TILE_B + r * SROW + cv * 16, src);
    }
}

__device__ __forceinline__ void gemm_core(uint32_t sb,
                                          const __half* __restrict__ Ah,
                                          const __half* __restrict__ Al,
                                          const __half* __restrict__ Bh,
                                          int m0, int n0, int tid,
                                          float acc[4][4][4])
{
    int wid = tid >> 5, lane = tid & 31;
    int warpM = wid & 1, warpN = wid >> 1;

#pragma unroll
    for (int i = 0; i < 4; i++)
#pragma unroll
        for (int j = 0; j < 4; j++)
#pragma unroll
            for (int c = 0; c < 4; c++) acc[i][j][c] = 0.f;

    int aRow = warpM * 64 + (lane & 15);
    int aColHalf = (lane >> 4) * 8;
    int bMat = lane >> 3;
    int bRow = warpN * 32 + (bMat >> 1) * 8 + (lane & 7);
    int bColHalf = (bMat & 1) * 8;

    const int NCHUNK = K_ / 32;

    gemm_issue_loads(sb, 0, Ah, Al, Bh, m0, n0, 0, tid);
    CP_COMMIT();

    for (int c = 0; c < NCHUNK; ++c) {
        if (c + 1 < NCHUNK) {
            gemm_issue_loads(sb, (c + 1) & 1, Ah, Al, Bh, m0, n0, (c + 1) * 32, tid);
            CP_COMMIT();
            CP_WAIT(1);
        } else {
            CP_WAIT(0);
        }
        __syncthreads();

        uint32_t st = sb + (c & 1) * STAGE_B;
        uint32_t tAh = st, tAl = st + TILE_B, tBh = st + 2 * TILE_B;

#pragma unroll
        for (int kk = 0; kk < 32; kk += 16) {
            uint32_t a[4][4], bh[4][2];
#pragma unroll
            for (int fm = 0; fm < 4; fm++) {
                uint32_t ad = tAh + (aRow + fm * 16) * SROW + (kk + aColHalf) * 2;
                LDSM_X4(a[fm][0], a[fm][1], a[fm][2], a[fm][3], ad);
            }
#pragma unroll
            for (int g = 0; g < 2; g++) {
                uint32_t bd = tBh + (bRow + g * 16) * SROW + (kk + bColHalf) * 2;
                LDSM_X4(bh[2 * g][0], bh[2 * g][1], bh[2 * g + 1][0], bh[2 * g + 1][1], bd);
            }
            // hi pass
#pragma unroll
            for (int fm = 0; fm < 4; fm++)
#pragma unroll
                for (int fn = 0; fn < 4; fn++)
                    MMA16816(acc[fm][fn], a[fm][0], a[fm][1], a[fm][2], a[fm][3],
                             bh[fn][0], bh[fn][1]);
            // lo-A pass (reuse a[] registers)
#pragma unroll
            for (int fm = 0; fm < 4; fm++) {
                uint32_t ad = tAl + (aRow + fm * 16) * SROW + (kk + aColHalf) * 2;
                LDSM_X4(a[fm][0], a[fm][1], a[fm][2], a[fm][3], ad);
            }
#pragma unroll
            for (int fm = 0; fm < 4; fm++)
#pragma unroll
                for (int fn = 0; fn < 4; fn++)
                    MMA16816(acc[fm][fn], a[fm][0], a[fm][1], a[fm][2], a[fm][3],
                             bh[fn][0], bh[fn][1]);
        }
        __syncthreads();
    }
}

// Fused Q/K/V projection: blockIdx.z selects weight + destination.
__global__ __launch_bounds__(256, 2) void gemm_qkv(const __half* __restrict__ Ah,
                                                   const __half* __restrict__ Al,
                                                   const __half* __restrict__ W0,   // wq|wk|wv contiguous
                                                   __half* __restrict__ qh, __half* __restrict__ ql,
                                                   __half* __restrict__ kh, __half* __restrict__ kl,
                                                   __half* __restrict__ vh)
{
    extern __shared__ char smem[];
    uint32_t sb = smem_u32(smem);
    int tid = threadIdx.x, wid = tid >> 5, lane = tid & 31;
    int m0 = blockIdx.y * 128, n0 = blockIdx.x * 128;
    int z = blockIdx.z;
    const __half* Bh = W0 + (size_t)z * D_ * D_;

    float acc[4][4][4];
    gemm_core(sb, Ah, Al, Bh, m0, n0, tid, acc);

    __half* Ch = (z == 0) ? qh : (z == 1) ? kh : vh;
    __half* Cl = (z == 0) ? ql : (z == 1) ? kl : (__half*)nullptr;
    float scale = (z == 0) ? 0.08838834764831845f : 1.0f;   // HD^-0.5 folded into Q

    int warpM = wid & 1, warpN = wid >> 1;
#pragma unroll
    for (int fm = 0; fm < 4; fm++) {
#pragma unroll
        for (int fn = 0; fn < 4; fn++) {
            int m = m0 + warpM * 64 + fm * 16 + (lane >> 2);
            int n = n0 + warpN * 32 + fn * 8 + (lane & 3) * 2;
#pragma unroll
            for (int half = 0; half < 2; half++) {
                int mr = m + half * 8;
                float v0 = acc[fm][fn][half * 2] * scale;
                float v1 = acc[fm][fn][half * 2 + 1] * scale;
                int b = mr >> 11, t = mr & (T_ - 1);
                int hhd = n >> 7, hd = n & (HD_ - 1);
                size_t off = (((size_t)((b * H_ + hhd) * T_ + t)) << 7) + hd;
                __half h0 = __float2half_rn(v0);
                __half h1 = __float2half_rn(v1);
                *(__half2*)(Ch + off) = __halves2half2(h0, h1);
                if (Cl) {
                    __half l0 = __float2half_rn(v0 - __half2float(h0));
                    __half l1 = __float2half_rn(v1 - __half2float(h1));
                    *(__half2*)(Cl + off) = __halves2half2(l0, l1);
                }
            }
        }
    }
}

// Output projection: fp32 row-major result.
__global__ __launch_bounds__(256, 2) void gemm_out(const __half* __restrict__ Ah,
                                                   const __half* __restrict__ Al,
                                                   const __half* __restrict__ Bh,
                                                   float* __restrict__ Cf)
{
    extern __shared__ char smem[];
    uint32_t sb = smem_u32(smem);
    int tid = threadIdx.x, wid = tid >> 5, lane = tid & 31;
    int m0 = blockIdx.y * 128, n0 = blockIdx.x * 128;

    float acc[4][4][4];
    gemm_core(sb, Ah, Al, Bh, m0, n0, tid, acc);

    int warpM = wid & 1, warpN = wid >> 1;
#pragma unroll
    for (int fm = 0; fm < 4; fm++) {
#pragma unroll
        for (int fn = 0; fn < 4; fn++) {
            int m = m0 + warpM * 64 + fm * 16 + (lane >> 2);
            int n = n0 + warpN * 32 + fn * 8 + (lane & 3) * 2;
#pragma unroll
            for (int half = 0; half < 2; half++) {
                int mr = m + half * 8;
                float2 o = {acc[fm][fn][half * 2], acc[fm][fn][half * 2 + 1]};
                *(float2*)(Cf + (size_t)mr * D_ + n) = o;
            }
        }
    }
}

// -------------------- Flash attention (causal, tensor cores) ----------------
// Br=128, Bc=64, 8 warps. QK^T: Q pair x K pair (3-pass). PV: P pair x V (2-pass).
// smem: Qh 0, Ql 34816, Kbuf 69632 (2 stages x 34816; Kl at +17408),
// Vt 139264 (128 x 144B, [hd][token], hi only), Ph 157696, Pl 176128. Tot 194560.
#define FL_QH  0
#define FL_QL  34816
#define FL_K0  69632
#define FL_VT  139264
#define FL_PH  157696
#define FL_PL  176128
#define FLASH_SMEM 194560

__global__ __launch_bounds__(256, 1) void flash_mma(
    const __half* __restrict__ Qh, const __half* __restrict__ Ql,
    const __half* __restrict__ Kh, const __half* __restrict__ Kl,
    const __half* __restrict__ Vh,
    __half* __restrict__ Oh, __half* __restrict__ Ol)
{
    extern __shared__ char smem[];
    uint32_t sb = smem_u32(smem);
    int tid = threadIdx.x, wid = tid >> 5, lane = tid & 31;
    int qt = (gridDim.x - 1) - blockIdx.x;   // heavy causal tiles scheduled first
    int bh = blockIdx.y;
    int q0 = qt * 128;
    size_t hbase = (size_t)bh * T_ * HD_;
    const __half *Qhp = Qh + hbase + (size_t)q0 * HD_;
    const __half *Qlp = Ql + hbase + (size_t)q0 * HD_;
    const __half *Khp = Kh + hbase, *Klp = Kl + hbase;
    const __half *Vhp = Vh + hbase;

    // Q tiles -> smem (async), rows padded to 272B
#pragma unroll
    for (int it = 0; it < 16; ++it) {
        int i = tid + it * 256;
        int hl = i >> 11, j = i & 2047;
        int r = j >> 4, c16 = j & 15;
        const __half* src = (hl ? Qlp : Qhp) + (size_t)r * HD_ + c16 * 8;
        CP_ASYNC16(sb + (hl ? FL_QL : FL_QH) + r * 272 + c16 * 16, src);
    }
    CP_COMMIT();

    // K tile 0 -> smem stage 0
#pragma unroll
    for (int it = 0; it < 8; ++it) {
        int i = tid + it * 256;
        int hl = i >> 10, j = i & 1023;
        int r = j >> 4, c16 = j & 15;
        const __half* src = (hl ? Klp : Khp) + (size_t)r * HD_ + c16 * 8;
        CP_ASYNC16(sb + FL_K0 + hl * 17408 + r * 272 + c16 * 16, src);
    }
    CP_COMMIT();

    // V tile 0 -> regs (thread: tokens 2*lane,2*lane+1; hd blocks wid*8, 64+wid*8)
    uint4 vha0, vhb0, vha1, vhb1;
    {
        const __half* s0 = Vhp + (size_t)(2 * lane) * HD_ + wid * 8;
        vha0 = *(const uint4*)(s0);
        vhb0 = *(const uint4*)(s0 + HD_);
        vha1 = *(const uint4*)(s0 + 64);
        vhb1 = *(const uint4*)(s0 + HD_ + 64);
    }

    float m_i[2] = {-1e30f, -1e30f}, l_i[2] = {0.f, 0.f};
    float o[16][4];
#pragma unroll
    for (int i = 0; i < 16; i++)
#pragma unroll
        for (int c = 0; c < 4; c++) o[i][c] = 0.f;

    const int aRow = lane & 15, aColH = (lane >> 4) * 8;
    const int bMat = lane >> 3;
    const int bRowB = ((bMat >> 1) * 8) + (lane & 7);
    const int bColH = (bMat & 1) * 8;
    int nkt = 2 * qt + 2;

    for (int kt = 0; kt < nkt; ++kt) {
        __syncthreads();          // prior-iter reads of Vt/Kbuf done
        CP_WAIT(0);               // K(kt) (and Q on iter 0) arrived

        // transpose-store V tile kt -> Vt smem [hd][token]
#pragma unroll
        for (int j = 0; j < 8; j++) {
            *(uint32_t*)(smem + FL_VT + (wid * 8 + j) * 144 + lane * 4) =
                u4_get(vha0, j) | (u4_get(vhb0, j) << 16);
            *(uint32_t*)(smem + FL_VT + (64 + wid * 8 + j) * 144 + lane * 4) =
                u4_get(vha1, j) | (u4_get(vhb1, j) << 16);
        }

        // prefetch K(kt+1) via cp.async and V(kt+1) into regs
        if (kt + 1 < nkt) {
            int k0n = (kt + 1) * 64;
#pragma unroll
            for (int it = 0; it < 8; ++it) {
                int i = tid + it * 256;
                int hl = i >> 10, j = i & 1023;
                int r = j >> 4, c16 = j & 15;
                const __half* src = (hl ? Klp : Khp) + (size_t)(k0n + r) * HD_ + c16 * 8;
                CP_ASYNC16(sb + FL_K0 + ((kt + 1) & 1) * 34816 + hl * 17408 + r * 272 + c16 * 16,
                           src);
            }
            CP_COMMIT();
            const __half* s0 = Vhp + (size_t)(k0n + 2 * lane) * HD_ + wid * 8;
            vha0 = *(const uint4*)(s0);
            vhb0 = *(const uint4*)(s0 + HD_);
            vha1 = *(const uint4*)(s0 + 64);
            vhb1 = *(const uint4*)(s0 + HD_ + 64);
        }
        __syncthreads();          // Vt visible to all warps

        // ---- S = Q @ K^T (3-pass: qh*kh + qh*kl + ql*kh) -------------------
        uint32_t kb = sb + FL_K0 + (kt & 1) * 34816;
        float sc[8][4];
#pragma unroll
        for (int i = 0; i < 8; i++)
#pragma unroll
            for (int c = 0; c < 4; c++) sc[i][c] = 0.f;

        uint32_t qha = sb + FL_QH + (wid * 16 + aRow) * 272 + aColH * 2;
        uint32_t qla = sb + FL_QL + (wid * 16 + aRow) * 272 + aColH * 2;
#pragma unroll
        for (int ks = 0; ks < 8; ++ks) {
            uint32_t a0, a1, a2, a3, e0, e1, e2, e3;
            LDSM_X4(a0, a1, a2, a3, qha + ks * 32);
            LDSM_X4(e0, e1, e2, e3, qla + ks * 32);
#pragma unroll
            for (int nf2 = 0; nf2 < 4; ++nf2) {
                uint32_t badr = kb + (nf2 * 16 + bRowB) * 272 + (ks * 16 + bColH) * 2;
                uint32_t b0, b1, b2, b3, c0, c1, c2, c3;
                LDSM_X4(b0, b1, b2, b3, badr);
                LDSM_X4(c0, c1, c2, c3, badr + 17408);
                MMA16816(sc[nf2 * 2 + 0], a0, a1, a2, a3, b0, b1);
                MMA16816(sc[nf2 * 2 + 1], a0, a1, a2, a3, b2, b3);
                MMA16816(sc[nf2 * 2 + 0], a0, a1, a2, a3, c0, c1);
                MMA16816(sc[nf2 * 2 + 1], a0, a1, a2, a3, c2, c3);
                MMA16816(sc[nf2 * 2 + 0], e0, e1, e2, e3, b0, b1);
                MMA16816(sc[nf2 * 2 + 1], e0, e1, e2, e3, b2, b3);
            }
        }

        // causal mask (diagonal-region tiles only)
        if (kt >= 2 * qt) {
            int r0 = q0 + wid * 16 + (lane >> 2);
            int cb = kt * 64 + (lane & 3) * 2;
#pragma unroll
            for (int nf = 0; nf < 8; ++nf)
#pragma unroll
                for (int c = 0; c < 4; ++c) {
                    int row = r0 + ((c >> 1) << 3);
                    int col = cb + nf * 8 + (c & 1);
                    if (col > row) sc[nf][c] = -1e30f;
                }
        }

        // ---- online softmax (2 rows per thread) ----------------------------
        float mt0 = -1e30f, mt1 = -1e30f;
#pragma unroll
        for (int nf = 0; nf < 8; ++nf) {
            mt0 = fmaxf(mt0, fmaxf(sc[nf][0], sc[nf][1]));
            mt1 = fmaxf(mt1, fmaxf(sc[nf][2], sc[nf][3]));
        }
        mt0 = fmaxf(mt0, __shfl_xor_sync(0xffffffffu, mt0, 1));
        mt0 = fmaxf(mt0, __shfl_xor_sync(0xffffffffu, mt0, 2));
        mt1 = fmaxf(mt1, __shfl_xor_sync(0xffffffffu, mt1, 1));
        mt1 = fmaxf(mt1, __shfl_xor_sync(0xffffffffu, mt1, 2));
        float mn0 = fmaxf(m_i[0], mt0), mn1 = fmaxf(m_i[1], mt1);
        float al0 = __expf(m_i[0] - mn0), al1 = __expf(m_i[1] - mn1);
        float ps0 = 0.f, ps1 = 0.f;
#pragma unroll
        for (int nf = 0; nf < 8; ++nf) {
            sc[nf][0] = __expf(sc[nf][0] - mn0); ps0 += sc[nf][0];
            sc[nf][1] = __expf(sc[nf][1] - mn0); ps0 += sc[nf][1];
            sc[nf][2] = __expf(sc[nf][2] - mn1); ps1 += sc[nf][2];
            sc[nf][3] = __expf(sc[nf][3] - mn1); ps1 += sc[nf][3];
        }
        ps0 += __shfl_xor_sync(0xffffffffu, ps0, 1);
        ps0 += __shfl_xor_sync(0xffffffffu, ps0, 2);
        ps1 += __shfl_xor_sync(0xffffffffu, ps1, 1);
        ps1 += __shfl_xor_sync(0xffffffffu, ps1, 2);
        l_i[0] = l_i[0] * al0 + ps0;  m_i[0] = mn0;
        l_i[1] = l_i[1] * al1 + ps1;  m_i[1] = mn1;
#pragma unroll
        for (int nf = 0; nf < 16; ++nf) {
            o[nf][0] *= al0; o[nf][1] *= al0;
            o[nf][2] *= al1; o[nf][3] *= al1;
        }

        // write P hi/lo to smem (own 16 rows only)
#pragma unroll
        for (int h = 0; h < 2; ++h) {
            int prow = wid * 16 + (lane >> 2) + 8 * h;
            int pcol = (lane & 3) * 2;
#pragma unroll
            for (int nf = 0; nf < 8; ++nf) {
                float p0 = sc[nf][2 * h], p1 = sc[nf][2 * h + 1];
                __half h0 = __float2half_rn(p0);
                __half h1 = __float2half_rn(p1);
                *(__half2*)(smem + FL_PH + prow * 144 + (nf * 8 + pcol) * 2) =
                    __halves2half2(h0, h1);
                __half l0 = __float2half_rn(p0 - __half2float(h0));
                __half l1 = __float2half_rn(p1 - __half2float(h1));
                *(__half2*)(smem + FL_PL + prow * 144 + (nf * 8 + pcol) * 2) =
                    __halves2half2(l0, l1);
            }
        }
        __syncwarp();

        // ---- O += P @ V (2-pass: (Ph+Pl) * Vh), m16 x n128 over k64 --------
        uint32_t pha = sb + FL_PH + (wid * 16 + aRow) * 144 + aColH * 2;
        uint32_t pla = sb + FL_PL + (wid * 16 + aRow) * 144 + aColH * 2;
#pragma unroll
        for (int ks = 0; ks < 4; ++ks) {
            uint32_t a0, a1, a2, a3, e0, e1, e2, e3;
            LDSM_X4(a0, a1, a2, a3, pha + ks * 32);
            LDSM_X4(e0, e1, e2, e3, pla + ks * 32);
#pragma unroll
            for (int nf2 = 0; nf2 < 8; ++nf2) {
                uint32_t vadr = sb + FL_VT + (nf2 * 16 + bRowB) * 144 + (ks * 16 + bColH) * 2;
                uint32_t b0, b1, b2, b3;
                LDSM_X4(b0, b1, b2, b3, vadr);
                MMA16816(o[nf2 * 2 + 0], a0, a1, a2, a3, b0, b1);
                MMA16816(o[nf2 * 2 + 1], a0, a1, a2, a3, b2, b3);
                MMA16816(o[nf2 * 2 + 0], e0, e1, e2, e3, b0, b1);
                MMA16816(o[nf2 * 2 + 1], e0, e1, e2, e3, b2, b3);
            }
        }
    }

    // epilogue: O /= l, write fp16 hi/lo to [B,T,D]
    int bb = bh >> 4, hh = bh & 15;
    float inv[2] = {1.f / l_i[0], 1.f / l_i[1]};
#pragma unroll
    for (int h = 0; h < 2; ++h) {
        int row = q0 + wid * 16 + (lane >> 2) + 8 * h;
        size_t rb = (size_t)(bb * T_ + row) * D_ + hh * HD_ + (lane & 3) * 2;
#pragma unroll
        for (int nf = 0; nf < 16; ++nf) {
            float v0 = o[nf][2 * h] * inv[h], v1 = o[nf][2 * h + 1] * inv[h];
            __half h0 = __float2half_rn(v0), h1 = __float2half_rn(v1);
            *(__half2*)(Oh + rb + nf * 8) = __halves2half2(h0, h1);
            __half L0 = __float2half_rn(v0 - __half2float(h0));
            __half L1 = __float2half_rn(v1 - __half2float(h1));
            *(__half2*)(Ol + rb + nf * 8) = __halves2half2(L0, L1);
        }
    }
}

// ------------------------------- launcher -----------------------------------
extern "C" void kernel_launch(void* const* d_in, const int* in_sizes, int n_in,
                              void* d_out, int out_size)
{
    const float* x      = (const float*)d_in[0];
    // d_in[1] = attn_mask (deterministic causal; applied analytically)
    const float* w_norm = (const float*)d_in[2];
    const float* wq     = (const float*)d_in[3];
    const float* wk     = (const float*)d_in[4];
    const float* wv     = (const float*)d_in[5];
    const float* wo     = (const float*)d_in[6];
    float* out = (float*)d_out;

    void *pxh, *pxl, *pwh, *pqh, *pql, *pkh, *pkl, *pvh, *pah, *pal;
    cudaGetSymbolAddress(&pxh, g_xnh);
    cudaGetSymbolAddress(&pxl, g_xnl);
    cudaGetSymbolAddress(&pwh, g_wh);
    cudaGetSymbolAddress(&pqh, g_qh);
    cudaGetSymbolAddress(&pql, g_ql);
    cudaGetSymbolAddress(&pkh, g_kh);
    cudaGetSymbolAddress(&pkl, g_kl);
    cudaGetSymbolAddress(&pvh, g_vh);
    cudaGetSymbolAddress(&pah, g_ah);
    cudaGetSymbolAddress(&pal, g_al);
    __half* xnh = (__half*)pxh;
    __half* xnl = (__half*)pxl;
    __half* wh  = (__half*)pwh;   // 4 contiguous [D*D] fp16 blocks
    __half* qh  = (__half*)pqh;
    __half* ql  = (__half*)pql;
    __half* kh  = (__half*)pkh;
    __half* kl  = (__half*)pkl;
    __half* vh  = (__half*)pvh;
    __half* ah  = (__half*)pah;
    __half* al  = (__half*)pal;

    cudaFuncSetAttribute(gemm_qkv, cudaFuncAttributeMaxDynamicSharedMemorySize, GEMM_SMEM);
    cudaFuncSetAttribute(gemm_out, cudaFuncAttributeMaxDynamicSharedMemorySize, GEMM_SMEM);
    cudaFuncSetAttribute(flash_mma, cudaFuncAttributeMaxDynamicSharedMemorySize, FLASH_SMEM);

    const size_t WSZ = (size_t)D_ * D_;
    const int wn4 = (int)(WSZ / 4);
    const float* wsrc[4] = {wq, wk, wv, wo};

    // 1) RMSNorm + fp16 hi/lo split
    rmsnorm_split_kernel<<<M_, 256>>>(x, w_norm, xnh, xnl);

    // 2) convert the 4 weight matrices to fp16
    for (int i = 0; i < 4; i++)
        convert_kernel<<<(wn4 + 255) / 256, 256>>>(wsrc[i], wh + i * WSZ, wn4);

    // 3) fused Q/K/V projections -> fp16 [B,H,T,HD]; HD^-0.5 folded into Q
    dim3 qkvgrid(D_ / 128, M_ / 128, 3);
    gemm_qkv<<<qkvgrid, 256, GEMM_SMEM>>>(xnh, xnl, wh, qh, ql, kh, kl, vh);

    // 4) causal flash attention on tensor cores -> fp16 hi/lo [B,T,D]
    dim3 fgrid(T_ / 128, B_ * H_);
    flash_mma<<<fgrid, 256, FLASH_SMEM>>>(qh, ql, kh, kl, vh, ah, al);

    // 5) output projection -> d_out (fp32)
    dim3 ggrid(D_ / 128, M_ / 128);
    gemm_out<<<ggrid, 256, GEMM_SMEM>>>(ah, al, wh + 3 * WSZ, out);
}

// round 16
// speedup vs baseline: 8.2698x; 1.2301x over previous
#include <cuda_runtime.h>
#include <cuda_fp16.h>
#include <cstdint>
#include <math.h>

#define B_   2
#define T_   2048
#define D_   2048
#define H_   16
#define HD_  128
#define M_   (B_ * T_)   // 4096
#define K_   2048

// ---------------- scratch (allocation-free: device globals) ----------------
__device__ __half g_xnh[(size_t)M_ * D_];
__device__ __half g_xnl[(size_t)M_ * D_];
__device__ __half g_wh [4][(size_t)D_ * D_];   // q,k,v,o (fp16 single)
__device__ __half g_qh [(size_t)M_ * D_];      // [B,H,T,HD]
__device__ __half g_ql [(size_t)M_ * D_];
__device__ __half g_kh [(size_t)M_ * D_];      // K: hi only
__device__ __half g_vh [(size_t)M_ * D_];      // V: hi only
__device__ __half g_ah [(size_t)M_ * D_];      // attention out [B,T,D] hi/lo
__device__ __half g_al [(size_t)M_ * D_];

// ------------------------- PTX helpers (baseline sm_103 ISA) ----------------
__device__ __forceinline__ uint32_t smem_u32(const void* p) {
    uint32_t a;
    asm("{ .reg .u64 t; cvta.to.shared.u64 t, %1; cvt.u32.u64 %0, t; }" : "=r"(a) : "l"(p));
    return a;
}

#define CP_ASYNC16(dst, src) \
    asm volatile("cp.async.cg.shared.global [%0], [%1], 16;" :: "r"(dst), "l"(src))
#define CP_COMMIT() asm volatile("cp.async.commit_group;" ::: "memory")
#define CP_WAIT(n)  asm volatile("cp.async.wait_group %0;" :: "n"(n) : "memory")

#define LDSM_X4(r0, r1, r2, r3, a) \
    asm volatile("ldmatrix.sync.aligned.m8n8.x4.shared.b16 {%0,%1,%2,%3}, [%4];" \
                 : "=r"(r0), "=r"(r1), "=r"(r2), "=r"(r3) : "r"(a))

#define MMA16816(d, a0, a1, a2, a3, b0, b1) \
    asm volatile("mma.sync.aligned.m16n8k16.row.col.f32.f16.f16.f32 " \
                 "{%0,%1,%2,%3}, {%4,%5,%6,%7}, {%8,%9}, {%0,%1,%2,%3};" \
                 : "+f"((d)[0]), "+f"((d)[1]), "+f"((d)[2]), "+f"((d)[3]) \
                 : "r"(a0), "r"(a1), "r"(a2), "r"(a3), "r"(b0), "r"(b1))

__device__ __forceinline__ uint32_t u4_get(const uint4& v, int j) {
    uint32_t w = ((j >> 1) == 0) ? v.x : ((j >> 1) == 1) ? v.y : ((j >> 1) == 2) ? v.z : v.w;
    return (j & 1) ? (w >> 16) : (w & 0xffffu);
}

// ---------------------- RMSNorm + split to fp16 hi/lo -----------------------
__global__ __launch_bounds__(256) void rmsnorm_split_kernel(const float* __restrict__ x,
                                                            const float* __restrict__ w,
                                                            __half* __restrict__ hi,
                                                            __half* __restrict__ lo)
{
    int row = blockIdx.x;
    const float* xr = x + (size_t)row * D_;
    int tid = threadIdx.x;

    float s = 0.f;
#pragma unroll
    for (int c = tid * 4; c < D_; c += 256 * 4) {
        float4 v = *(const float4*)(xr + c);
        s += v.x * v.x + v.y * v.y + v.z * v.z + v.w * v.w;
    }
#pragma unroll
    for (int m = 16; m; m >>= 1) s += __shfl_xor_sync(0xffffffffu, s, m);

    __shared__ float red[8];
    __shared__ float totsh;
    if ((tid & 31) == 0) red[tid >> 5] = s;
    __syncthreads();
    if (tid == 0) {
        float t = 0.f;
#pragma unroll
        for (int i = 0; i < 8; i++) t += red[i];
        totsh = t;
    }
    __syncthreads();

    float norm = sqrtf(totsh) * 0.022097086912079608f;  // * D^-0.5
    float inv  = 1.0f / (norm + 1e-8f);

#pragma unroll
    for (int c = tid * 4; c < D_; c += 256 * 4) {
        float4 v  = *(const float4*)(xr + c);
        float4 wv = *(const float4*)(w + c);
        float o[4] = {wv.x * v.x * inv, wv.y * v.y * inv, wv.z * v.z * inv, wv.w * v.w * inv};
#pragma unroll
        for (int j = 0; j < 4; j++) {
            __half h = __float2half_rn(o[j]);
            float r = o[j] - __half2float(h);
            hi[(size_t)row * D_ + c + j] = h;
            lo[(size_t)row * D_ + c + j] = __float2half_rn(r);
        }
    }
}

// ----------------- fp32 -> fp16 convert (all 4 weights, one launch) ---------
__global__ __launch_bounds__(256) void convert4_kernel(const float* __restrict__ w0,
                                                       const float* __restrict__ w1,
                                                       const float* __restrict__ w2,
                                                       const float* __restrict__ w3,
                                                       __half* __restrict__ hi,
                                                       int n4)
{
    int i = blockIdx.x * 256 + threadIdx.x;
    if (i >= n4) return;
    int z = blockIdx.y;
    const float* x = (z == 0) ? w0 : (z == 1) ? w1 : (z == 2) ? w2 : w3;
    __half* dst = hi + (size_t)z * D_ * D_;
    float4 v = ((const float4*)x)[i];
    __half2 p0 = __halves2half2(__float2half_rn(v.x), __float2half_rn(v.y));
    __half2 p1 = __halves2half2(__float2half_rn(v.z), __float2half_rn(v.w));
    ((__half2*)dst)[i * 2 + 0] = p0;
    ((__half2*)dst)[i * 2 + 1] = p1;
}

// ------ warp-MMA GEMM core: acc = (Ah[+Al])[M,K] @ Bh[N,K]^T  (fp16) --------
#define SROW     80
#define TILE_B   (128 * SROW)            // 10240
#define STAGE_B  (3 * TILE_B)            // Ah, (Al), Bh
#define GEMM_SMEM (2 * STAGE_B)          // 61440

template <bool LO>
__device__ __forceinline__ void gemm_issue_loads(uint32_t sb, int stage,
                                                 const __half* Ah, const __half* Al,
                                                 const __half* Bh,
                                                 int m0, int n0, int k0, int tid)
{
    uint32_t base = sb + stage * STAGE_B;
    const int NIT = LO ? 6 : 4;
#pragma unroll
    for (int it = 0; it < NIT; ++it) {
        int i = tid + it * 256;
        int tile, j;
        if (LO) { tile = i >> 9; j = i & 511; }            // 0:Ah 1:Al 2:Bh
        else    { tile = (i >> 9) * 2; j = i & 511; }      // 0:Ah 2:Bh
        int r = j >> 2, cv = j & 3;
        int row0 = (tile < 2) ? m0 : n0;
        const __half* srcp = (tile == 0) ? Ah : (tile == 1) ? Al : Bh;
        const __half* src = srcp + (size_t)(row0 + r) * K_ + k0 + cv * 8;
        CP_ASYNC16(base + tile * TILE_B + r * SROW + cv * 16, src);
    }
}

template <bool LO>
__device__ __forceinline__ void gemm_core(uint32_t sb,
                                          const __half* __restrict__ Ah,
                                          const __half* __restrict__ Al,
                                          const __half* __restrict__ Bh,
                                          int m0, int n0, int tid,
                                          float acc[4][4][4])
{
    int wid = tid >> 5, lane = tid & 31;
    int warpM = wid & 1, warpN = wid >> 1;

#pragma unroll
    for (int i = 0; i < 4; i++)
#pragma unroll
        for (int j = 0; j < 4; j++)
#pragma unroll
            for (int c = 0; c < 4; c++) acc[i][j][c] = 0.f;

    int aRow = warpM * 64 + (lane & 15);
    int aColHalf = (lane >> 4) * 8;
    int bMat = lane >> 3;
    int bRow = warpN * 32 + (bMat >> 1) * 8 + (lane & 7);
    int bColHalf = (bMat & 1) * 8;

    const int NCHUNK = K_ / 32;

    gemm_issue_loads<LO>(sb, 0, Ah, Al, Bh, m0, n0, 0, tid);
    CP_COMMIT();

    for (int c = 0; c < NCHUNK; ++c) {
        if (c + 1 < NCHUNK) {
            gemm_issue_loads<LO>(sb, (c + 1) & 1, Ah, Al, Bh, m0, n0, (c + 1) * 32, tid);
            CP_COMMIT();
            CP_WAIT(1);
        } else {
            CP_WAIT(0);
        }
        __syncthreads();

        uint32_t st = sb + (c & 1) * STAGE_B;
        uint32_t tAh = st, tAl = st + TILE_B, tBh = st + 2 * TILE_B;

#pragma unroll
        for (int kk = 0; kk < 32; kk += 16) {
            uint32_t a[4][4], bh[4][2];
#pragma unroll
            for (int fm = 0; fm < 4; fm++) {
                uint32_t ad = tAh + (aRow + fm * 16) * SROW + (kk + aColHalf) * 2;
                LDSM_X4(a[fm][0], a[fm][1], a[fm][2], a[fm][3], ad);
            }
#pragma unroll
            for (int g = 0; g < 2; g++) {
                uint32_t bd = tBh + (bRow + g * 16) * SROW + (kk + bColHalf) * 2;
                LDSM_X4(bh[2 * g][0], bh[2 * g][1], bh[2 * g + 1][0], bh[2 * g + 1][1], bd);
            }
            // hi pass
#pragma unroll
            for (int fm = 0; fm < 4; fm++)
#pragma unroll
                for (int fn = 0; fn < 4; fn++)
                    MMA16816(acc[fm][fn], a[fm][0], a[fm][1], a[fm][2], a[fm][3],
                             bh[fn][0], bh[fn][1]);
            if (LO) {
                // lo-A pass (reuse a[] registers)
#pragma unroll
                for (int fm = 0; fm < 4; fm++) {
                    uint32_t ad = tAl + (aRow + fm * 16) * SROW + (kk + aColHalf) * 2;
                    LDSM_X4(a[fm][0], a[fm][1], a[fm][2], a[fm][3], ad);
                }
#pragma unroll
                for (int fm = 0; fm < 4; fm++)
#pragma unroll
                    for (int fn = 0; fn < 4; fn++)
                        MMA16816(acc[fm][fn], a[fm][0], a[fm][1], a[fm][2], a[fm][3],
                                 bh[fn][0], bh[fn][1]);
            }
        }
        __syncthreads();
    }
}

// Fused Q/K/V projection: blockIdx.z selects weight + destination + pass count.
// z=0 (Q): 1-pass, split hi/lo output, HD^-0.5 folded.  z=1 (K): 1-pass, hi only.
// z=2 (V): 2-pass, hi only.
__global__ __launch_bounds__(256, 2) void gemm_qkv(const __half* __restrict__ Ah,
                                                   const __half* __restrict__ Al,
                                                   const __half* __restrict__ W0,
                                                   __half* __restrict__ qh, __half* __restrict__ ql,
                                                   __half* __restrict__ kh,
                                                   __half* __restrict__ vh)
{
    extern __shared__ char smem[];
    uint32_t sb = smem_u32(smem);
    int tid = threadIdx.x, wid = tid >> 5, lane = tid & 31;
    int m0 = blockIdx.y * 128, n0 = blockIdx.x * 128;
    int z = blockIdx.z;
    const __half* Bh = W0 + (size_t)z * D_ * D_;

    float acc[4][4][4];
    if (z == 2) gemm_core<true >(sb, Ah, Al, Bh, m0, n0, tid, acc);
    else        gemm_core<false>(sb, Ah, Al, Bh, m0, n0, tid, acc);

    __half* Ch = (z == 0) ? qh : (z == 1) ? kh : vh;
    __half* Cl = (z == 0) ? ql : (__half*)nullptr;
    float scale = (z == 0) ? 0.08838834764831845f : 1.0f;

    int warpM = wid & 1, warpN = wid >> 1;
#pragma unroll
    for (int fm = 0; fm < 4; fm++) {
#pragma unroll
        for (int fn = 0; fn < 4; fn++) {
            int m = m0 + warpM * 64 + fm * 16 + (lane >> 2);
            int n = n0 + warpN * 32 + fn * 8 + (lane & 3) * 2;
#pragma unroll
            for (int half = 0; half < 2; half++) {
                int mr = m + half * 8;
                float v0 = acc[fm][fn][half * 2] * scale;
                float v1 = acc[fm][fn][half * 2 + 1] * scale;
                int b = mr >> 11, t = mr & (T_ - 1);
                int hhd = n >> 7, hd = n & (HD_ - 1);
                size_t off = (((size_t)((b * H_ + hhd) * T_ + t)) << 7) + hd;
                __half h0 = __float2half_rn(v0);
                __half h1 = __float2half_rn(v1);
                *(__half2*)(Ch + off) = __halves2half2(h0, h1);
                if (Cl) {
                    __half l0 = __float2half_rn(v0 - __half2float(h0));
                    __half l1 = __float2half_rn(v1 - __half2float(h1));
                    *(__half2*)(Cl + off) = __halves2half2(l0, l1);
                }
            }
        }
    }
}

// Output projection: 2-pass, fp32 row-major result.
__global__ __launch_bounds__(256, 2) void gemm_out(const __half* __restrict__ Ah,
                                                   const __half* __restrict__ Al,
                                                   const __half* __restrict__ Bh,
                                                   float* __restrict__ Cf)
{
    extern __shared__ char smem[];
    uint32_t sb = smem_u32(smem);
    int tid = threadIdx.x, wid = tid >> 5, lane = tid & 31;
    int m0 = blockIdx.y * 128, n0 = blockIdx.x * 128;

    float acc[4][4][4];
    gemm_core<true>(sb, Ah, Al, Bh, m0, n0, tid, acc);

    int warpM = wid & 1, warpN = wid >> 1;
#pragma unroll
    for (int fm = 0; fm < 4; fm++) {
#pragma unroll
        for (int fn = 0; fn < 4; fn++) {
            int m = m0 + warpM * 64 + fm * 16 + (lane >> 2);
            int n = n0 + warpN * 32 + fn * 8 + (lane & 3) * 2;
#pragma unroll
            for (int half = 0; half < 2; half++) {
                int mr = m + half * 8;
                float2 o = {acc[fm][fn][half * 2], acc[fm][fn][half * 2 + 1]};
                *(float2*)(Cf + (size_t)mr * D_ + n) = o;
            }
        }
    }
}

// -------------------- Flash attention (causal, tensor cores) ----------------
// Br=128, Bc=64, 8 warps. QK^T: (Qh+Ql) x Kh (2-pass). PV: (Ph+Pl) x Vh (2-pass).
// smem: Qh 0 (34816), Ql 34816, Kbuf 69632 (2 stages x 17408),
// Vt 104448 (128 x 144B, [hd][token]), Ph 122880, Pl 141312. Total 159744.
#define FL_QH  0
#define FL_QL  34816
#define FL_K0  69632
#define FL_VT  104448
#define FL_PH  122880
#define FL_PL  141312
#define FLASH_SMEM 159744

__global__ __launch_bounds__(256, 1) void flash_mma(
    const __half* __restrict__ Qh, const __half* __restrict__ Ql,
    const __half* __restrict__ Kh,
    const __half* __restrict__ Vh,
    __half* __restrict__ Oh, __half* __restrict__ Ol)
{
    extern __shared__ char smem[];
    uint32_t sb = smem_u32(smem);
    int tid = threadIdx.x, wid = tid >> 5, lane = tid & 31;
    int qt = (gridDim.x - 1) - blockIdx.x;   // heavy causal tiles first
    int bh = blockIdx.y;
    int q0 = qt * 128;
    size_t hbase = (size_t)bh * T_ * HD_;
    const __half *Qhp = Qh + hbase + (size_t)q0 * HD_;
    const __half *Qlp = Ql + hbase + (size_t)q0 * HD_;
    const __half *Khp = Kh + hbase;
    const __half *Vhp = Vh + hbase;

    // Q tiles -> smem (async), rows padded to 272B
#pragma unroll
    for (int it = 0; it < 16; ++it) {
        int i = tid + it * 256;
        int hl = i >> 11, j = i & 2047;
        int r = j >> 4, c16 = j & 15;
        const __half* src = (hl ? Qlp : Qhp) + (size_t)r * HD_ + c16 * 8;
        CP_ASYNC16(sb + (hl ? FL_QL : FL_QH) + r * 272 + c16 * 16, src);
    }
    CP_COMMIT();

    // K tile 0 -> smem stage 0 (hi only: 64 rows x 16 vectors)
#pragma unroll
    for (int it = 0; it < 4; ++it) {
        int i = tid + it * 256;
        int r = i >> 4, c16 = i & 15;
        CP_ASYNC16(sb + FL_K0 + r * 272 + c16 * 16, Khp + (size_t)r * HD_ + c16 * 8);
    }
    CP_COMMIT();

    // V tile 0 -> regs
    uint4 vha0, vhb0, vha1, vhb1;
    {
        const __half* s0 = Vhp + (size_t)(2 * lane) * HD_ + wid * 8;
        vha0 = *(const uint4*)(s0);
        vhb0 = *(const uint4*)(s0 + HD_);
        vha1 = *(const uint4*)(s0 + 64);
        vhb1 = *(const uint4*)(s0 + HD_ + 64);
    }

    float m_i[2] = {-1e30f, -1e30f}, l_i[2] = {0.f, 0.f};
    float o[16][4];
#pragma unroll
    for (int i = 0; i < 16; i++)
#pragma unroll
        for (int c = 0; c < 4; c++) o[i][c] = 0.f;

    const int aRow = lane & 15, aColH = (lane >> 4) * 8;
    const int bMat = lane >> 3;
    const int bRowB = ((bMat >> 1) * 8) + (lane & 7);
    const int bColH = (bMat & 1) * 8;
    int nkt = 2 * qt + 2;

    for (int kt = 0; kt < nkt; ++kt) {
        __syncthreads();          // prior-iter reads of Vt/Kbuf done
        CP_WAIT(0);               // K(kt) (and Q on iter 0) arrived

        // transpose-store V tile kt -> Vt smem [hd][token]
#pragma unroll
        for (int j = 0; j < 8; j++) {
            *(uint32_t*)(smem + FL_VT + (wid * 8 + j) * 144 + lane * 4) =
                u4_get(vha0, j) | (u4_get(vhb0, j) << 16);
            *(uint32_t*)(smem + FL_VT + (64 + wid * 8 + j) * 144 + lane * 4) =
                u4_get(vha1, j) | (u4_get(vhb1, j) << 16);
        }

        // prefetch K(kt+1) via cp.async and V(kt+1) into regs
        if (kt + 1 < nkt) {
            int k0n = (kt + 1) * 64;
#pragma unroll
            for (int it = 0; it < 4; ++it) {
                int i = tid + it * 256;
                int r = i >> 4, c16 = i & 15;
                CP_ASYNC16(sb + FL_K0 + ((kt + 1) & 1) * 17408 + r * 272 + c16 * 16,
                           Khp + (size_t)(k0n + r) * HD_ + c16 * 8);
            }
            CP_COMMIT();
            const __half* s0 = Vhp + (size_t)(k0n + 2 * lane) * HD_ + wid * 8;
            vha0 = *(const uint4*)(s0);
            vhb0 = *(const uint4*)(s0 + HD_);
            vha1 = *(const uint4*)(s0 + 64);
            vhb1 = *(const uint4*)(s0 + HD_ + 64);
        }
        __syncthreads();          // Vt visible to all warps

        // ---- S = Q @ K^T (2-pass: qh*kh + ql*kh) ---------------------------
        uint32_t kb = sb + FL_K0 + (kt & 1) * 17408;
        float sc[8][4];
#pragma unroll
        for (int i = 0; i < 8; i++)
#pragma unroll
            for (int c = 0; c < 4; c++) sc[i][c] = 0.f;

        uint32_t qha = sb + FL_QH + (wid * 16 + aRow) * 272 + aColH * 2;
        uint32_t qla = sb + FL_QL + (wid * 16 + aRow) * 272 + aColH * 2;
#pragma unroll
        for (int ks = 0; ks < 8; ++ks) {
            uint32_t a0, a1, a2, a3, e0, e1, e2, e3;
            LDSM_X4(a0, a1, a2, a3, qha + ks * 32);
            LDSM_X4(e0, e1, e2, e3, qla + ks * 32);
#pragma unroll
            for (int nf2 = 0; nf2 < 4; ++nf2) {
                uint32_t badr = kb + (nf2 * 16 + bRowB) * 272 + (ks * 16 + bColH) * 2;
                uint32_t b0, b1, b2, b3;
                LDSM_X4(b0, b1, b2, b3, badr);
                MMA16816(sc[nf2 * 2 + 0], a0, a1, a2, a3, b0, b1);
                MMA16816(sc[nf2 * 2 + 1], a0, a1, a2, a3, b2, b3);
                MMA16816(sc[nf2 * 2 + 0], e0, e1, e2, e3, b0, b1);
                MMA16816(sc[nf2 * 2 + 1], e0, e1, e2, e3, b2, b3);
            }
        }

        // causal mask (diagonal-region tiles only)
        if (kt >= 2 * qt) {
            int r0 = q0 + wid * 16 + (lane >> 2);
            int cb = kt * 64 + (lane & 3) * 2;
#pragma unroll
            for (int nf = 0; nf < 8; ++nf)
#pragma unroll
                for (int c = 0; c < 4; ++c) {
                    int row = r0 + ((c >> 1) << 3);
                    int col = cb + nf * 8 + (c & 1);
                    if (col > row) sc[nf][c] = -1e30f;
                }
        }

        // ---- online softmax (2 rows per thread) ----------------------------
        float mt0 = -1e30f, mt1 = -1e30f;
#pragma unroll
        for (int nf = 0; nf < 8; ++nf) {
            mt0 = fmaxf(mt0, fmaxf(sc[nf][0], sc[nf][1]));
            mt1 = fmaxf(mt1, fmaxf(sc[nf][2], sc[nf][3]));
        }
        mt0 = fmaxf(mt0, __shfl_xor_sync(0xffffffffu, mt0, 1));
        mt0 = fmaxf(mt0, __shfl_xor_sync(0xffffffffu, mt0, 2));
        mt1 = fmaxf(mt1, __shfl_xor_sync(0xffffffffu, mt1, 1));
        mt1 = fmaxf(mt1, __shfl_xor_sync(0xffffffffu, mt1, 2));
        float mn0 = fmaxf(m_i[0], mt0), mn1 = fmaxf(m_i[1], mt1);
        float al0 = __expf(m_i[0] - mn0), al1 = __expf(m_i[1] - mn1);
        float ps0 = 0.f, ps1 = 0.f;
#pragma unroll
        for (int nf = 0; nf < 8; ++nf) {
            sc[nf][0] = __expf(sc[nf][0] - mn0); ps0 += sc[nf][0];
            sc[nf][1] = __expf(sc[nf][1] - mn0); ps0 += sc[nf][1];
            sc[nf][2] = __expf(sc[nf][2] - mn1); ps1 += sc[nf][2];
            sc[nf][3] = __expf(sc[nf][3] - mn1); ps1 += sc[nf][3];
        }
        ps0 += __shfl_xor_sync(0xffffffffu, ps0, 1);
        ps0 += __shfl_xor_sync(0xffffffffu, ps0, 2);
        ps1 += __shfl_xor_sync(0xffffffffu, ps1, 1);
        ps1 += __shfl_xor_sync(0xffffffffu, ps1, 2);
        l_i[0] = l_i[0] * al0 + ps0;  m_i[0] = mn0;
        l_i[1] = l_i[1] * al1 + ps1;  m_i[1] = mn1;
#pragma unroll
        for (int nf = 0; nf < 16; ++nf) {
            o[nf][0] *= al0; o[nf][1] *= al0;
            o[nf][2] *= al1; o[nf][3] *= al1;
        }

        // write P hi/lo to smem (own 16 rows only)
#pragma unroll
        for (int h = 0; h < 2; ++h) {
            int prow = wid * 16 + (lane >> 2) + 8 * h;
            int pcol = (lane & 3) * 2;
#pragma unroll
            for (int nf = 0; nf < 8; ++nf) {
                float p0 = sc[nf][2 * h], p1 = sc[nf][2 * h + 1];
                __half h0 = __float2half_rn(p0);
                __half h1 = __float2half_rn(p1);
                *(__half2*)(smem + FL_PH + prow * 144 + (nf * 8 + pcol) * 2) =
                    __halves2half2(h0, h1);
                __half l0 = __float2half_rn(p0 - __half2float(h0));
                __half l1 = __float2half_rn(p1 - __half2float(h1));
                *(__half2*)(smem + FL_PL + prow * 144 + (nf * 8 + pcol) * 2) =
                    __halves2half2(l0, l1);
            }
        }
        __syncwarp();

        // ---- O += P @ V (2-pass: (Ph+Pl) * Vh), m16 x n128 over k64 --------
        uint32_t pha = sb + FL_PH + (wid * 16 + aRow) * 144 + aColH * 2;
        uint32_t pla = sb + FL_PL + (wid * 16 + aRow) * 144 + aColH * 2;
#pragma unroll
        for (int ks = 0; ks < 4; ++ks) {
            uint32_t a0, a1, a2, a3, e0, e1, e2, e3;
            LDSM_X4(a0, a1, a2, a3, pha + ks * 32);
            LDSM_X4(e0, e1, e2, e3, pla + ks * 32);
#pragma unroll
            for (int nf2 = 0; nf2 < 8; ++nf2) {
                uint32_t vadr = sb + FL_VT + (nf2 * 16 + bRowB) * 144 + (ks * 16 + bColH) * 2;
                uint32_t b0, b1, b2, b3;
                LDSM_X4(b0, b1, b2, b3, vadr);
                MMA16816(o[nf2 * 2 + 0], a0, a1, a2, a3, b0, b1);
                MMA16816(o[nf2 * 2 + 1], a0, a1, a2, a3, b2, b3);
                MMA16816(o[nf2 * 2 + 0], e0, e1, e2, e3, b0, b1);
                MMA16816(o[nf2 * 2 + 1], e0, e1, e2, e3, b2, b3);
            }
        }
    }

    // epilogue: O /= l, write fp16 hi/lo to [B,T,D]
    int bb = bh >> 4, hh = bh & 15;
    float inv[2] = {1.f / l_i[0], 1.f / l_i[1]};
#pragma unroll
    for (int h = 0; h < 2; ++h) {
        int row = q0 + wid * 16 + (lane >> 2) + 8 * h;
        size_t rb = (size_t)(bb * T_ + row) * D_ + hh * HD_ + (lane & 3) * 2;
#pragma unroll
        for (int nf = 0; nf < 16; ++nf) {
            float v0 = o[nf][2 * h] * inv[h], v1 = o[nf][2 * h + 1] * inv[h];
            __half h0 = __float2half_rn(v0), h1 = __float2half_rn(v1);
            *(__half2*)(Oh + rb + nf * 8) = __halves2half2(h0, h1);
            __half L0 = __float2half_rn(v0 - __half2float(h0));
            __half L1 = __float2half_rn(v1 - __half2float(h1));
            *(__half2*)(Ol + rb + nf * 8) = __halves2half2(L0, L1);
        }
    }
}

// ------------------------------- launcher -----------------------------------
extern "C" void kernel_launch(void* const* d_in, const int* in_sizes, int n_in,
                              void* d_out, int out_size)
{
    const float* x      = (const float*)d_in[0];
    // d_in[1] = attn_mask (deterministic causal; applied analytically)
    const float* w_norm = (const float*)d_in[2];
    const float* wq     = (const float*)d_in[3];
    const float* wk     = (const float*)d_in[4];
    const float* wv     = (const float*)d_in[5];
    const float* wo     = (const float*)d_in[6];
    float* out = (float*)d_out;

    void *pxh, *pxl, *pwh, *pqh, *pql, *pkh, *pvh, *pah, *pal;
    cudaGetSymbolAddress(&pxh, g_xnh);
    cudaGetSymbolAddress(&pxl, g_xnl);
    cudaGetSymbolAddress(&pwh, g_wh);
    cudaGetSymbolAddress(&pqh, g_qh);
    cudaGetSymbolAddress(&pql, g_ql);
    cudaGetSymbolAddress(&pkh, g_kh);
    cudaGetSymbolAddress(&pvh, g_vh);
    cudaGetSymbolAddress(&pah, g_ah);
    cudaGetSymbolAddress(&pal, g_al);
    __half* xnh = (__half*)pxh;
    __half* xnl = (__half*)pxl;
    __half* wh  = (__half*)pwh;   // 4 contiguous [D*D] fp16 blocks
    __half* qh  = (__half*)pqh;
    __half* ql  = (__half*)pql;
    __half* kh  = (__half*)pkh;
    __half* vh  = (__half*)pvh;
    __half* ah  = (__half*)pah;
    __half* al  = (__half*)pal;

    cudaFuncSetAttribute(gemm_qkv, cudaFuncAttributeMaxDynamicSharedMemorySize, GEMM_SMEM);
    cudaFuncSetAttribute(gemm_out, cudaFuncAttributeMaxDynamicSharedMemorySize, GEMM_SMEM);
    cudaFuncSetAttribute(flash_mma, cudaFuncAttributeMaxDynamicSharedMemorySize, FLASH_SMEM);

    const size_t WSZ = (size_t)D_ * D_;
    const int wn4 = (int)(WSZ / 4);

    // 1) RMSNorm + fp16 hi/lo split
    rmsnorm_split_kernel<<<M_, 256>>>(x, w_norm, xnh, xnl);

    // 2) convert the 4 weight matrices to fp16 (one launch)
    dim3 cgrid((wn4 + 255) / 256, 4);
    convert4_kernel<<<cgrid, 256>>>(wq, wk, wv, wo, wh, wn4);

    // 3) fused Q/K/V projections (Q,K 1-pass; V 2-pass) -> fp16 [B,H,T,HD]
    dim3 qkvgrid(D_ / 128, M_ / 128, 3);
    gemm_qkv<<<qkvgrid, 256, GEMM_SMEM>>>(xnh, xnl, wh, qh, ql, kh, vh);

    // 4) causal flash attention (QK 2-pass, PV 2-pass) -> fp16 hi/lo [B,T,D]
    dim3 fgrid(T_ / 128, B_ * H_);
    flash_mma<<<fgrid, 256, FLASH_SMEM>>>(qh, ql, kh, vh, ah, al);

    // 5) output projection (2-pass) -> d_out (fp32)
    dim3 ggrid(D_ / 128, M_ / 128);
    gemm_out<<<ggrid, 256, GEMM_SMEM>>>(ah, al, wh + 3 * WSZ, out);
}